// round 1
// baseline (speedup 1.0000x reference)
#include <cuda_runtime.h>
#include <cuda_bf16.h>
#include <math.h>

// Problem constants
#define BB 2
#define SS 2048
#define DD 2048
#define HH 16
#define HD 128
#define CHUNK 1024
#define ROWS (BB*SS)          // 4096
#define QKVN (3*DD)           // 6144
#define FFN  (4*DD)           // 8192

// ---------------- scratch (static device globals; no runtime alloc) ----------
__device__ float g_ln [(size_t)ROWS*DD];        // LN output (reused for LN1 and LN2)
__device__ float g_qkv[(size_t)ROWS*QKVN];      // qkv projection
__device__ float g_att[(size_t)ROWS*DD];        // attention output (B,S,H*HD)
__device__ float g_x2 [(size_t)ROWS*DD];        // x + attn_out (residual stream)
__device__ float g_act[(size_t)ROWS*FFN];       // gelu(h@w1+b1)

// ---------------- LayerNorm: one block per row, D=2048, 256 threads ----------
__global__ __launch_bounds__(256) void ln_kernel(const float* __restrict__ x,
                                                 const float* __restrict__ g,
                                                 const float* __restrict__ be,
                                                 float* __restrict__ y)
{
    const int row = blockIdx.x;
    const int tid = threadIdx.x;
    const float* xr = x + (size_t)row * DD;

    float4 v0 = *(const float4*)&xr[tid * 4];
    float4 v1 = *(const float4*)&xr[1024 + tid * 4];

    float s  = v0.x + v0.y + v0.z + v0.w + v1.x + v1.y + v1.z + v1.w;
    float ss = v0.x*v0.x + v0.y*v0.y + v0.z*v0.z + v0.w*v0.w
             + v1.x*v1.x + v1.y*v1.y + v1.z*v1.z + v1.w*v1.w;

    #pragma unroll
    for (int o = 16; o > 0; o >>= 1) {
        s  += __shfl_xor_sync(0xffffffffu, s,  o);
        ss += __shfl_xor_sync(0xffffffffu, ss, o);
    }
    __shared__ float rs[8], rss[8];
    __shared__ float mean_s, rstd_s;
    const int w = tid >> 5, ln = tid & 31;
    if (ln == 0) { rs[w] = s; rss[w] = ss; }
    __syncthreads();
    if (tid == 0) {
        float S = 0.f, SSQ = 0.f;
        #pragma unroll
        for (int i = 0; i < 8; i++) { S += rs[i]; SSQ += rss[i]; }
        float mean = S * (1.0f / DD);
        float var  = SSQ * (1.0f / DD) - mean * mean;
        mean_s = mean;
        rstd_s = rsqrtf(var + 1e-5f);
    }
    __syncthreads();
    const float mean = mean_s, rstd = rstd_s;

    float4 g0  = *(const float4*)&g [tid * 4];
    float4 g1  = *(const float4*)&g [1024 + tid * 4];
    float4 b0  = *(const float4*)&be[tid * 4];
    float4 b1  = *(const float4*)&be[1024 + tid * 4];

    float4 o0, o1;
    o0.x = (v0.x - mean) * rstd * g0.x + b0.x;
    o0.y = (v0.y - mean) * rstd * g0.y + b0.y;
    o0.z = (v0.z - mean) * rstd * g0.z + b0.z;
    o0.w = (v0.w - mean) * rstd * g0.w + b0.w;
    o1.x = (v1.x - mean) * rstd * g1.x + b1.x;
    o1.y = (v1.y - mean) * rstd * g1.y + b1.y;
    o1.z = (v1.z - mean) * rstd * g1.z + b1.z;
    o1.w = (v1.w - mean) * rstd * g1.w + b1.w;

    float* yr = y + (size_t)row * DD;
    *(float4*)&yr[tid * 4]        = o0;
    *(float4*)&yr[1024 + tid * 4] = o1;
}

// ---------------- SGEMM: C[M,N] = A[M,K] @ B[K,N] (+epilogue) ---------------
// 128x128 tile, BK=8, 256 threads, 8x8 per thread (split-64 fragments).
#define EPI_NONE       0
#define EPI_RESID      1
#define EPI_BIAS_GELU  2
#define EPI_BIAS_RESID 3

template<int EPI>
__global__ __launch_bounds__(256) void sgemm_kernel(
    const float* __restrict__ A, const float* __restrict__ B,
    float* __restrict__ C,
    const float* __restrict__ bias, const float* __restrict__ resid,
    int M, int N, int K)
{
    __shared__ float As[8][132];   // padded to kill transpose-store conflicts
    __shared__ float Bs[8][128];

    const int tid = threadIdx.x;
    const int row0 = blockIdx.y * 128;
    const int col0 = blockIdx.x * 128;

    const int a_r = tid >> 1, a_c = (tid & 1) * 4;   // A: 128 rows x 8 cols
    const int b_r = tid >> 5, b_c = (tid & 31) * 4;  // B: 8 rows x 128 cols
    const int tx = tid & 15, ty = tid >> 4;

    float acc[8][8];
    #pragma unroll
    for (int i = 0; i < 8; i++)
        #pragma unroll
        for (int j = 0; j < 8; j++) acc[i][j] = 0.f;

    const float* Ap = A + (size_t)(row0 + a_r) * K + a_c;
    const float* Bp = B + (size_t)b_r * N + col0 + b_c;

    for (int k0 = 0; k0 < K; k0 += 8) {
        float4 av = *(const float4*)Ap;
        float4 bv = *(const float4*)Bp;
        As[a_c + 0][a_r] = av.x;
        As[a_c + 1][a_r] = av.y;
        As[a_c + 2][a_r] = av.z;
        As[a_c + 3][a_r] = av.w;
        *(float4*)&Bs[b_r][b_c] = bv;
        __syncthreads();

        #pragma unroll
        for (int kk = 0; kk < 8; kk++) {
            float a0[4], a1[4], b0[4], b1[4];
            *(float4*)a0 = *(const float4*)&As[kk][ty * 4];
            *(float4*)a1 = *(const float4*)&As[kk][64 + ty * 4];
            *(float4*)b0 = *(const float4*)&Bs[kk][tx * 4];
            *(float4*)b1 = *(const float4*)&Bs[kk][64 + tx * 4];
            #pragma unroll
            for (int i = 0; i < 4; i++) {
                #pragma unroll
                for (int j = 0; j < 4; j++) {
                    acc[i][j]         += a0[i] * b0[j];
                    acc[i][j + 4]     += a0[i] * b1[j];
                    acc[i + 4][j]     += a1[i] * b0[j];
                    acc[i + 4][j + 4] += a1[i] * b1[j];
                }
            }
        }
        __syncthreads();
        Ap += 8;
        Bp += (size_t)8 * N;
    }

    // epilogue + store
    #pragma unroll
    for (int i = 0; i < 8; i++) {
        const int r = row0 + ((i < 4) ? (ty * 4 + i) : (64 + ty * 4 + i - 4));
        #pragma unroll
        for (int jh = 0; jh < 2; jh++) {
            const int c = col0 + (jh ? (64 + tx * 4) : (tx * 4));
            float vr[4];
            #pragma unroll
            for (int j = 0; j < 4; j++) {
                float val = acc[i][jh * 4 + j];
                const int col = c + j;
                if (EPI == EPI_BIAS_GELU || EPI == EPI_BIAS_RESID) val += bias[col];
                if (EPI == EPI_RESID || EPI == EPI_BIAS_RESID)
                    val += resid[(size_t)r * N + col];
                if (EPI == EPI_BIAS_GELU)
                    val = 0.5f * val * (1.0f + erff(val * 0.70710678118654752f));
                vr[j] = val;
            }
            *(float4*)&C[(size_t)r * N + c] = *(float4*)vr;
        }
    }
}

// ---------------- Attention (flash-style, chunk mask j <= q%1024) -----------
// grid: (S/64 = 32 q-tiles, B*H = 32). block: 256 threads.
// Thread t: query q_local = t/4, owns dims [lane4*32, lane4*32+32).
__global__ __launch_bounds__(256) void attn_kernel(const float* __restrict__ qkv,
                                                   float* __restrict__ out)
{
    extern __shared__ float sm[];
    float* Ks = sm;                    // 64*128
    float* Vs = sm + 64 * 128;         // 64*128
    float* Sc = sm + 2 * 64 * 128;     // 64*65 (padded)

    const int tid = threadIdx.x;
    const int qt  = blockIdx.x;        // 0..31
    const int bh  = blockIdx.y;        // 0..31
    const int b   = bh >> 4, h = bh & 15;
    const int ql  = tid >> 2, lane4 = tid & 3;
    const int qglob = qt * 64 + ql;
    const int qmod  = qglob & (CHUNK - 1);
    const float scale = 0.08838834764831845f;  // 1/sqrt(128)

    const float* qptr = qkv + (size_t)(b * SS + qglob) * QKVN + h * HD + lane4 * 32;
    float qf[32];
    #pragma unroll
    for (int i = 0; i < 32; i += 4) {
        float4 v = *(const float4*)&qptr[i];
        qf[i] = v.x; qf[i+1] = v.y; qf[i+2] = v.z; qf[i+3] = v.w;
    }

    float acc[32];
    #pragma unroll
    for (int i = 0; i < 32; i++) acc[i] = 0.f;
    float m = -1e30f, l = 0.f;

    const int nkt = (qt & 15) + 1;     // number of 64-key tiles needed
    for (int kt = 0; kt < nkt; kt++) {
        const int kb = kt * 64;
        // cooperative K/V tile load: 64 rows x 128 dims each
        #pragma unroll
        for (int i = 0; i < 8; i++) {
            const int idx = tid + 256 * i;       // float4 index, 0..2047
            const int r = idx >> 5, c4 = (idx & 31) << 2;
            const float* kp = qkv + (size_t)(b * SS + kb + r) * QKVN + DD + h * HD + c4;
            *(float4*)&Ks[r * 128 + c4] = *(const float4*)kp;
            *(float4*)&Vs[r * 128 + c4] = *(const float4*)(kp + DD);
        }
        __syncthreads();

        // scores for this tile
        for (int k = 0; k < 64; k++) {
            float p = 0.f;
            const float* kr = &Ks[k * 128 + lane4 * 32];
            #pragma unroll
            for (int i = 0; i < 32; i += 4) {
                float4 kv = *(const float4*)&kr[i];
                p += qf[i] * kv.x + qf[i+1] * kv.y + qf[i+2] * kv.z + qf[i+3] * kv.w;
            }
            p += __shfl_xor_sync(0xffffffffu, p, 1);
            p += __shfl_xor_sync(0xffffffffu, p, 2);
            if (lane4 == 0)
                Sc[ql * 65 + k] = (kb + k <= qmod) ? p * scale : -1e30f;
        }
        __syncwarp();

        float mt = -1e30f;
        for (int k = 0; k < 64; k++) mt = fmaxf(mt, Sc[ql * 65 + k]);
        const float mnew  = fmaxf(m, mt);
        const float alpha = __expf(m - mnew);
        #pragma unroll
        for (int i = 0; i < 32; i++) acc[i] *= alpha;

        float lsum = 0.f;
        for (int k = 0; k < 64; k++) {
            const float p = __expf(Sc[ql * 65 + k] - mnew);
            lsum += p;
            const float* vr = &Vs[k * 128 + lane4 * 32];
            #pragma unroll
            for (int i = 0; i < 32; i += 4) {
                float4 vv = *(const float4*)&vr[i];
                acc[i]   += p * vv.x;
                acc[i+1] += p * vv.y;
                acc[i+2] += p * vv.z;
                acc[i+3] += p * vv.w;
            }
        }
        l = l * alpha + lsum;
        m = mnew;
        __syncthreads();   // before next tile overwrites Ks/Vs
    }

    const float inv = 1.0f / l;
    float* op = out + (size_t)(b * SS + qglob) * DD + h * HD + lane4 * 32;
    #pragma unroll
    for (int i = 0; i < 32; i += 4) {
        float4 v;
        v.x = acc[i] * inv; v.y = acc[i+1] * inv;
        v.z = acc[i+2] * inv; v.w = acc[i+3] * inv;
        *(float4*)&op[i] = v;
    }
}

// ---------------- launch ----------------------------------------------------
extern "C" void kernel_launch(void* const* d_in, const int* in_sizes, int n_in,
                              void* d_out, int out_size)
{
    const float* x     = (const float*)d_in[0];
    const float* w_qkv = (const float*)d_in[1];
    const float* w_o   = (const float*)d_in[2];
    const float* w1    = (const float*)d_in[3];
    const float* b1    = (const float*)d_in[4];
    const float* w2    = (const float*)d_in[5];
    const float* b2    = (const float*)d_in[6];
    const float* g1    = (const float*)d_in[7];
    const float* be1   = (const float*)d_in[8];
    const float* g2    = (const float*)d_in[9];
    const float* be2   = (const float*)d_in[10];
    float* out = (float*)d_out;

    float *p_ln, *p_qkv, *p_att, *p_x2, *p_act;
    cudaGetSymbolAddress((void**)&p_ln,  g_ln);
    cudaGetSymbolAddress((void**)&p_qkv, g_qkv);
    cudaGetSymbolAddress((void**)&p_att, g_att);
    cudaGetSymbolAddress((void**)&p_x2,  g_x2);
    cudaGetSymbolAddress((void**)&p_act, g_act);

    const int attn_smem = (2 * 64 * 128 + 64 * 65) * 4;   // 82176 B
    cudaFuncSetAttribute(attn_kernel,
                         cudaFuncAttributeMaxDynamicSharedMemorySize, attn_smem);

    // 1) LN1
    ln_kernel<<<ROWS, 256>>>(x, g1, be1, p_ln);

    // 2) qkv = ln1 @ w_qkv   [4096 x 6144]
    sgemm_kernel<EPI_NONE><<<dim3(QKVN / 128, ROWS / 128), 256>>>(
        p_ln, w_qkv, p_qkv, nullptr, nullptr, ROWS, QKVN, DD);

    // 3) attention
    attn_kernel<<<dim3(SS / 64, BB * HH), 256, attn_smem>>>(p_qkv, p_att);

    // 4) x2 = attn_out @ w_o + x
    sgemm_kernel<EPI_RESID><<<dim3(DD / 128, ROWS / 128), 256>>>(
        p_att, w_o, p_x2, nullptr, x, ROWS, DD, DD);

    // 5) LN2
    ln_kernel<<<ROWS, 256>>>(p_x2, g2, be2, p_ln);

    // 6) act = gelu(ln2 @ w1 + b1)   [4096 x 8192]
    sgemm_kernel<EPI_BIAS_GELU><<<dim3(FFN / 128, ROWS / 128), 256>>>(
        p_ln, w1, p_act, b1, nullptr, ROWS, FFN, DD);

    // 7) out = act @ w2 + b2 + x2
    sgemm_kernel<EPI_BIAS_RESID><<<dim3(DD / 128, ROWS / 128), 256>>>(
        p_act, w2, out, b2, p_x2, ROWS, DD, FFN);
}

// round 3
// speedup vs baseline: 1.8333x; 1.8333x over previous
#include <cuda_runtime.h>
#include <cuda_bf16.h>
#include <math.h>
#include <stdint.h>

// Problem constants
#define BB 2
#define SS 2048
#define DD 2048
#define HH 16
#define HD 128
#define CHUNK 1024
#define ROWS (BB*SS)          // 4096
#define QKVN (3*DD)           // 6144
#define FFN  (4*DD)           // 8192

// ---------------- scratch (static device globals; no runtime alloc) ----------
__device__ float g_ln [(size_t)ROWS*DD];
__device__ float g_qkv[(size_t)ROWS*QKVN];
__device__ float g_att[(size_t)ROWS*DD];
__device__ float g_x2 [(size_t)ROWS*DD];
__device__ float g_act[(size_t)ROWS*FFN];
// tf32-rounded weights (same [K,N] layout as inputs)
__device__ float g_wqkv_r[(size_t)DD*QKVN];
__device__ float g_wo_r [(size_t)DD*DD];
__device__ float g_w1_r [(size_t)DD*FFN];
__device__ float g_w2_r [(size_t)FFN*DD];

// ---------------- helpers ----------------------------------------------------
__device__ __forceinline__ float rtf32(float x) {
    uint32_t u;
    asm("cvt.rna.tf32.f32 %0, %1;" : "=r"(u) : "f"(x));
    return __uint_as_float(u);
}
__device__ __forceinline__ void cpasync16(void* s, const void* g) {
    uint32_t a;
    asm("{ .reg .u64 t; cvta.to.shared.u64 t, %1; cvt.u32.u64 %0, t; }"
        : "=r"(a) : "l"(s));
    asm volatile("cp.async.cg.shared.global [%0], [%1], 16;" :: "r"(a), "l"(g));
}
__device__ __forceinline__ void mma_tf32(float* c, const uint32_t* a, const uint32_t* b) {
    asm volatile(
        "mma.sync.aligned.m16n8k8.row.col.f32.tf32.tf32.f32 "
        "{%0,%1,%2,%3}, {%4,%5,%6,%7}, {%8,%9}, {%0,%1,%2,%3};"
        : "+f"(c[0]), "+f"(c[1]), "+f"(c[2]), "+f"(c[3])
        : "r"(a[0]), "r"(a[1]), "r"(a[2]), "r"(a[3]), "r"(b[0]), "r"(b[1]));
}

// ---------------- weight tf32 rounding (one elementwise pass) ----------------
__global__ __launch_bounds__(256) void round_kernel(const float* __restrict__ s,
                                                    float* __restrict__ d, int n4)
{
    const int i = blockIdx.x * 256 + threadIdx.x;
    if (i < n4) {
        float4 v = *(const float4*)(s + (size_t)i * 4);
        v.x = rtf32(v.x); v.y = rtf32(v.y); v.z = rtf32(v.z); v.w = rtf32(v.w);
        *(float4*)(d + (size_t)i * 4) = v;
    }
}

// ---------------- LayerNorm (tf32-rounded output) ----------------------------
__global__ __launch_bounds__(256) void ln_kernel(const float* __restrict__ x,
                                                 const float* __restrict__ g,
                                                 const float* __restrict__ be,
                                                 float* __restrict__ y)
{
    const int row = blockIdx.x;
    const int tid = threadIdx.x;
    const float* xr = x + (size_t)row * DD;

    float4 v0 = *(const float4*)&xr[tid * 4];
    float4 v1 = *(const float4*)&xr[1024 + tid * 4];

    float s  = v0.x + v0.y + v0.z + v0.w + v1.x + v1.y + v1.z + v1.w;
    float ss = v0.x*v0.x + v0.y*v0.y + v0.z*v0.z + v0.w*v0.w
             + v1.x*v1.x + v1.y*v1.y + v1.z*v1.z + v1.w*v1.w;

    #pragma unroll
    for (int o = 16; o > 0; o >>= 1) {
        s  += __shfl_xor_sync(0xffffffffu, s,  o);
        ss += __shfl_xor_sync(0xffffffffu, ss, o);
    }
    __shared__ float rs[8], rss[8];
    __shared__ float mean_s, rstd_s;
    const int w = tid >> 5, ln = tid & 31;
    if (ln == 0) { rs[w] = s; rss[w] = ss; }
    __syncthreads();
    if (tid == 0) {
        float S = 0.f, SSQ = 0.f;
        #pragma unroll
        for (int i = 0; i < 8; i++) { S += rs[i]; SSQ += rss[i]; }
        float mean = S * (1.0f / DD);
        float var  = SSQ * (1.0f / DD) - mean * mean;
        mean_s = mean;
        rstd_s = rsqrtf(var + 1e-5f);
    }
    __syncthreads();
    const float mean = mean_s, rstd = rstd_s;

    float4 g0  = *(const float4*)&g [tid * 4];
    float4 g1  = *(const float4*)&g [1024 + tid * 4];
    float4 b0  = *(const float4*)&be[tid * 4];
    float4 b1  = *(const float4*)&be[1024 + tid * 4];

    float4 o0, o1;
    o0.x = rtf32((v0.x - mean) * rstd * g0.x + b0.x);
    o0.y = rtf32((v0.y - mean) * rstd * g0.y + b0.y);
    o0.z = rtf32((v0.z - mean) * rstd * g0.z + b0.z);
    o0.w = rtf32((v0.w - mean) * rstd * g0.w + b0.w);
    o1.x = rtf32((v1.x - mean) * rstd * g1.x + b1.x);
    o1.y = rtf32((v1.y - mean) * rstd * g1.y + b1.y);
    o1.z = rtf32((v1.z - mean) * rstd * g1.z + b1.z);
    o1.w = rtf32((v1.w - mean) * rstd * g1.w + b1.w);

    float* yr = y + (size_t)row * DD;
    *(float4*)&yr[tid * 4]        = o0;
    *(float4*)&yr[1024 + tid * 4] = o1;
}

// ---------------- mma.sync tf32 GEMM: C = A[M,K] @ B[K,N] (+epilogue) --------
// 128x128 tile, BK=32, 256 threads (8 warps, 64x32 warp tiles), double buffer.
#define EPI_NONE       0
#define EPI_RESID      1
#define EPI_BIAS_GELU  2
#define EPI_BIAS_RESID 3

#define AS_STRIDE 36
#define BS_STRIDE 132
#define AS_BYTES  (128 * AS_STRIDE * 4)     // 18432
#define BS_BYTES  (32 * BS_STRIDE * 4)      // 16896
#define STAGE_BYTES (AS_BYTES + BS_BYTES)   // 35328
#define GEMM_SMEM (2 * STAGE_BYTES)         // 70656

template<int EPI>
__global__ __launch_bounds__(256, 2)
void mm_tf32(const float* __restrict__ A, const float* __restrict__ B,
             float* __restrict__ C, const float* __restrict__ bias,
             const float* __restrict__ resid, int M, int N, int K)
{
    extern __shared__ char dyn[];

    const int tid = threadIdx.x;
    const int wid = tid >> 5, lane = tid & 31;
    const int grp = lane >> 2, thr4 = lane & 3;
    const int wm = (wid & 1) * 64;       // warp row offset in tile
    const int wn = (wid >> 1) * 32;      // warp col offset in tile
    const int row0 = blockIdx.y * 128, col0 = blockIdx.x * 128;

    // load slots
    const int am  = tid >> 1;            // with i-offset below
    const int ak4 = tid & 1;
    const int bk  = tid >> 5;
    const int bn4 = tid & 31;

    const float* Ab = A + (size_t)row0 * K;
    const float* Bb = B + col0;

    float acc[4][4][4];
    #pragma unroll
    for (int mi = 0; mi < 4; mi++)
        #pragma unroll
        for (int ni = 0; ni < 4; ni++)
            #pragma unroll
            for (int q = 0; q < 4; q++) acc[mi][ni][q] = 0.f;

    const int nk = K >> 5;

    // ---- load stage: A 128x32 (1024 float4), B 32x128 (1024 float4) ----
    auto load_stage = [&](int kt, int buf) {
        char* sb = dyn + buf * STAGE_BYTES;
        float* As = (float*)sb;
        float* Bs = (float*)(sb + AS_BYTES);
        const float* ga = Ab + (size_t)kt * 32;
        const float* gb = Bb + (size_t)kt * 32 * N;
        #pragma unroll
        for (int i = 0; i < 4; i++) {
            const int m  = am + i * 64;               // 0..127
            const int k4 = ak4 + ((i & 0) );          // see below
            // A: idx = tid + 256*i -> m = idx>>3? use direct form instead:
            (void)m; (void)k4;
        }
        // A: 4 float4 per thread: idx = tid + 256*i, m = idx>>3, k4 = idx&7
        #pragma unroll
        for (int i = 0; i < 4; i++) {
            const int idx = tid + 256 * i;
            const int m = idx >> 3, k4 = idx & 7;
            cpasync16(&As[m * AS_STRIDE + k4 * 4], ga + (size_t)m * K + k4 * 4);
        }
        // B: 4 float4 per thread: idx = tid + 256*i, k = idx>>5, n4 = idx&31
        #pragma unroll
        for (int i = 0; i < 4; i++) {
            const int idx = tid + 256 * i;
            const int k = idx >> 5, n4 = idx & 31;
            cpasync16(&Bs[k * BS_STRIDE + n4 * 4], gb + (size_t)k * N + n4 * 4);
        }
        asm volatile("cp.async.commit_group;");
    };

    load_stage(0, 0);

    for (int kt = 0; kt < nk; kt++) {
        const int cur = kt & 1;
        if (kt + 1 < nk) {
            load_stage(kt + 1, cur ^ 1);
            asm volatile("cp.async.wait_group 1;");
        } else {
            asm volatile("cp.async.wait_group 0;");
        }
        __syncthreads();

        char* sb = dyn + cur * STAGE_BYTES;
        const float* As = (const float*)sb;
        const float* Bs = (const float*)(sb + AS_BYTES);

        #pragma unroll
        for (int kk = 0; kk < 32; kk += 8) {
            uint32_t afr[4][4], bfr[4][2];
            #pragma unroll
            for (int mi = 0; mi < 4; mi++) {
                const int m = wm + mi * 16 + grp;
                afr[mi][0] = __float_as_uint(As[m * AS_STRIDE + kk + thr4]);
                afr[mi][1] = __float_as_uint(As[(m + 8) * AS_STRIDE + kk + thr4]);
                afr[mi][2] = __float_as_uint(As[m * AS_STRIDE + kk + thr4 + 4]);
                afr[mi][3] = __float_as_uint(As[(m + 8) * AS_STRIDE + kk + thr4 + 4]);
            }
            #pragma unroll
            for (int ni = 0; ni < 4; ni++) {
                const int n = wn + ni * 8 + grp;
                bfr[ni][0] = __float_as_uint(Bs[(kk + thr4) * BS_STRIDE + n]);
                bfr[ni][1] = __float_as_uint(Bs[(kk + thr4 + 4) * BS_STRIDE + n]);
            }
            #pragma unroll
            for (int mi = 0; mi < 4; mi++)
                #pragma unroll
                for (int ni = 0; ni < 4; ni++)
                    mma_tf32(acc[mi][ni], afr[mi], bfr[ni]);
        }
        __syncthreads();
    }

    // ---- epilogue ----
    #pragma unroll
    for (int mi = 0; mi < 4; mi++) {
        #pragma unroll
        for (int half = 0; half < 2; half++) {
            const int r = row0 + wm + mi * 16 + grp + half * 8;
            #pragma unroll
            for (int ni = 0; ni < 4; ni++) {
                const int c = col0 + wn + ni * 8 + thr4 * 2;
                float v0 = acc[mi][ni][half * 2 + 0];
                float v1 = acc[mi][ni][half * 2 + 1];
                if (EPI == EPI_BIAS_GELU || EPI == EPI_BIAS_RESID) {
                    v0 += bias[c]; v1 += bias[c + 1];
                }
                if (EPI == EPI_RESID || EPI == EPI_BIAS_RESID) {
                    const float2 rr = *(const float2*)&resid[(size_t)r * N + c];
                    v0 += rr.x; v1 += rr.y;
                }
                if (EPI == EPI_BIAS_GELU) {
                    v0 = rtf32(0.5f * v0 * (1.0f + erff(v0 * 0.70710678118654752f)));
                    v1 = rtf32(0.5f * v1 * (1.0f + erff(v1 * 0.70710678118654752f)));
                }
                float2 o; o.x = v0; o.y = v1;
                *(float2*)&C[(size_t)r * N + c] = o;
            }
        }
    }
}

// ---------------- Attention (flash-style, chunk mask j <= q%1024) -----------
__global__ __launch_bounds__(256) void attn_kernel(const float* __restrict__ qkv,
                                                   float* __restrict__ out)
{
    extern __shared__ float sm[];
    float* Ks = sm;
    float* Vs = sm + 64 * 128;
    float* Sc = sm + 2 * 64 * 128;

    const int tid = threadIdx.x;
    const int qt  = blockIdx.x;
    const int bh  = blockIdx.y;
    const int b   = bh >> 4, h = bh & 15;
    const int ql  = tid >> 2, lane4 = tid & 3;
    const int qglob = qt * 64 + ql;
    const int qmod  = qglob & (CHUNK - 1);
    const float scale = 0.08838834764831845f;

    const float* qptr = qkv + (size_t)(b * SS + qglob) * QKVN + h * HD + lane4 * 32;
    float qf[32];
    #pragma unroll
    for (int i = 0; i < 32; i += 4) {
        float4 v = *(const float4*)&qptr[i];
        qf[i] = v.x; qf[i+1] = v.y; qf[i+2] = v.z; qf[i+3] = v.w;
    }

    float acc[32];
    #pragma unroll
    for (int i = 0; i < 32; i++) acc[i] = 0.f;
    float m = -1e30f, l = 0.f;

    const int nkt = (qt & 15) + 1;
    for (int kt = 0; kt < nkt; kt++) {
        const int kb = kt * 64;
        #pragma unroll
        for (int i = 0; i < 8; i++) {
            const int idx = tid + 256 * i;
            const int rr = idx >> 5, c4 = (idx & 31) << 2;
            const float* kp = qkv + (size_t)(b * SS + kb + rr) * QKVN + DD + h * HD + c4;
            *(float4*)&Ks[rr * 128 + c4] = *(const float4*)kp;
            *(float4*)&Vs[rr * 128 + c4] = *(const float4*)(kp + DD);
        }
        __syncthreads();

        for (int k = 0; k < 64; k++) {
            float p = 0.f;
            const float* kr = &Ks[k * 128 + lane4 * 32];
            #pragma unroll
            for (int i = 0; i < 32; i += 4) {
                float4 kv = *(const float4*)&kr[i];
                p += qf[i] * kv.x + qf[i+1] * kv.y + qf[i+2] * kv.z + qf[i+3] * kv.w;
            }
            p += __shfl_xor_sync(0xffffffffu, p, 1);
            p += __shfl_xor_sync(0xffffffffu, p, 2);
            if (lane4 == 0)
                Sc[ql * 65 + k] = (kb + k <= qmod) ? p * scale : -1e30f;
        }
        __syncwarp();

        float mt = -1e30f;
        for (int k = 0; k < 64; k++) mt = fmaxf(mt, Sc[ql * 65 + k]);
        const float mnew  = fmaxf(m, mt);
        const float alpha = __expf(m - mnew);
        #pragma unroll
        for (int i = 0; i < 32; i++) acc[i] *= alpha;

        float lsum = 0.f;
        for (int k = 0; k < 64; k++) {
            const float p = __expf(Sc[ql * 65 + k] - mnew);
            lsum += p;
            const float* vr = &Vs[k * 128 + lane4 * 32];
            #pragma unroll
            for (int i = 0; i < 32; i += 4) {
                float4 vv = *(const float4*)&vr[i];
                acc[i]   += p * vv.x;
                acc[i+1] += p * vv.y;
                acc[i+2] += p * vv.z;
                acc[i+3] += p * vv.w;
            }
        }
        l = l * alpha + lsum;
        m = mnew;
        __syncthreads();
    }

    const float inv = 1.0f / l;
    float* op = out + (size_t)(b * SS + qglob) * DD + h * HD + lane4 * 32;
    #pragma unroll
    for (int i = 0; i < 32; i += 4) {
        float4 v;
        v.x = rtf32(acc[i] * inv);   v.y = rtf32(acc[i+1] * inv);
        v.z = rtf32(acc[i+2] * inv); v.w = rtf32(acc[i+3] * inv);
        *(float4*)&op[i] = v;
    }
}

// ---------------- launch ----------------------------------------------------
extern "C" void kernel_launch(void* const* d_in, const int* in_sizes, int n_in,
                              void* d_out, int out_size)
{
    const float* x     = (const float*)d_in[0];
    const float* w_qkv = (const float*)d_in[1];
    const float* w_o   = (const float*)d_in[2];
    const float* w1    = (const float*)d_in[3];
    const float* b1    = (const float*)d_in[4];
    const float* w2    = (const float*)d_in[5];
    const float* b2    = (const float*)d_in[6];
    const float* g1    = (const float*)d_in[7];
    const float* be1   = (const float*)d_in[8];
    const float* g2    = (const float*)d_in[9];
    const float* be2   = (const float*)d_in[10];
    float* out = (float*)d_out;

    float *p_ln, *p_qkv, *p_att, *p_x2, *p_act;
    float *p_wqkv, *p_wo, *p_w1, *p_w2;
    cudaGetSymbolAddress((void**)&p_ln,  g_ln);
    cudaGetSymbolAddress((void**)&p_qkv, g_qkv);
    cudaGetSymbolAddress((void**)&p_att, g_att);
    cudaGetSymbolAddress((void**)&p_x2,  g_x2);
    cudaGetSymbolAddress((void**)&p_act, g_act);
    cudaGetSymbolAddress((void**)&p_wqkv, g_wqkv_r);
    cudaGetSymbolAddress((void**)&p_wo,   g_wo_r);
    cudaGetSymbolAddress((void**)&p_w1,   g_w1_r);
    cudaGetSymbolAddress((void**)&p_w2,   g_w2_r);

    const int attn_smem = (2 * 64 * 128 + 64 * 65) * 4;
    cudaFuncSetAttribute(attn_kernel,
                         cudaFuncAttributeMaxDynamicSharedMemorySize, attn_smem);
    cudaFuncSetAttribute(mm_tf32<EPI_NONE>,
                         cudaFuncAttributeMaxDynamicSharedMemorySize, GEMM_SMEM);
    cudaFuncSetAttribute(mm_tf32<EPI_RESID>,
                         cudaFuncAttributeMaxDynamicSharedMemorySize, GEMM_SMEM);
    cudaFuncSetAttribute(mm_tf32<EPI_BIAS_GELU>,
                         cudaFuncAttributeMaxDynamicSharedMemorySize, GEMM_SMEM);
    cudaFuncSetAttribute(mm_tf32<EPI_BIAS_RESID>,
                         cudaFuncAttributeMaxDynamicSharedMemorySize, GEMM_SMEM);

    // 0) round weights to tf32 once
    round_kernel<<<(DD*QKVN/4 + 255)/256, 256>>>(w_qkv, p_wqkv, DD*QKVN/4);
    round_kernel<<<(DD*DD/4   + 255)/256, 256>>>(w_o,   p_wo,   DD*DD/4);
    round_kernel<<<(DD*FFN/4  + 255)/256, 256>>>(w1,    p_w1,   DD*FFN/4);
    round_kernel<<<(FFN*DD/4  + 255)/256, 256>>>(w2,    p_w2,   FFN*DD/4);

    // 1) LN1
    ln_kernel<<<ROWS, 256>>>(x, g1, be1, p_ln);

    // 2) qkv = ln1 @ w_qkv
    mm_tf32<EPI_NONE><<<dim3(QKVN/128, ROWS/128), 256, GEMM_SMEM>>>(
        p_ln, p_wqkv, p_qkv, nullptr, nullptr, ROWS, QKVN, DD);

    // 3) attention
    attn_kernel<<<dim3(SS/64, BB*HH), 256, attn_smem>>>(p_qkv, p_att);

    // 4) x2 = attn_out @ w_o + x
    mm_tf32<EPI_RESID><<<dim3(DD/128, ROWS/128), 256, GEMM_SMEM>>>(
        p_att, p_wo, p_x2, nullptr, x, ROWS, DD, DD);

    // 5) LN2
    ln_kernel<<<ROWS, 256>>>(p_x2, g2, be2, p_ln);

    // 6) act = gelu(ln2 @ w1 + b1)
    mm_tf32<EPI_BIAS_GELU><<<dim3(FFN/128, ROWS/128), 256, GEMM_SMEM>>>(
        p_ln, p_w1, p_act, b1, nullptr, ROWS, FFN, DD);

    // 7) out = act @ w2 + b2 + x2
    mm_tf32<EPI_BIAS_RESID><<<dim3(DD/128, ROWS/128), 256, GEMM_SMEM>>>(
        p_act, p_w2, out, b2, p_x2, ROWS, DD, FFN);
}

// round 4
// speedup vs baseline: 4.4130x; 2.4072x over previous
#include <cuda_runtime.h>
#include <cuda_bf16.h>
#include <math.h>
#include <stdint.h>

// Problem constants
#define BB 2
#define SS 2048
#define DD 2048
#define HH 16
#define HD 128
#define CHUNK 1024
#define ROWS (BB*SS)          // 4096
#define QKVN (3*DD)           // 6144
#define FFN  (4*DD)           // 8192

// ---------------- scratch (static device globals; no runtime alloc) ----------
__device__ float g_ln [(size_t)ROWS*DD];
__device__ float g_qkv[(size_t)ROWS*QKVN];
__device__ float g_att[(size_t)ROWS*DD];
__device__ float g_x2 [(size_t)ROWS*DD];
__device__ float g_act[(size_t)ROWS*FFN];
__device__ float g_wqkv_r[(size_t)DD*QKVN];
__device__ float g_wo_r [(size_t)DD*DD];
__device__ float g_w1_r [(size_t)DD*FFN];
__device__ float g_w2_r [(size_t)FFN*DD];

// ---------------- helpers ----------------------------------------------------
__device__ __forceinline__ float rtf32(float x) {
    uint32_t u;
    asm("cvt.rna.tf32.f32 %0, %1;" : "=r"(u) : "f"(x));
    return __uint_as_float(u);
}
__device__ __forceinline__ void cpasync16(void* s, const void* g) {
    uint32_t a;
    asm("{ .reg .u64 t; cvta.to.shared.u64 t, %1; cvt.u32.u64 %0, t; }"
        : "=r"(a) : "l"(s));
    asm volatile("cp.async.cg.shared.global [%0], [%1], 16;" :: "r"(a), "l"(g));
}
__device__ __forceinline__ void mma_tf32(float* c, const uint32_t* a, const uint32_t* b) {
    asm volatile(
        "mma.sync.aligned.m16n8k8.row.col.f32.tf32.tf32.f32 "
        "{%0,%1,%2,%3}, {%4,%5,%6,%7}, {%8,%9}, {%0,%1,%2,%3};"
        : "+f"(c[0]), "+f"(c[1]), "+f"(c[2]), "+f"(c[3])
        : "r"(a[0]), "r"(a[1]), "r"(a[2]), "r"(a[3]), "r"(b[0]), "r"(b[1]));
}

// ---------------- weight tf32 rounding ---------------------------------------
__global__ __launch_bounds__(256) void round_kernel(const float* __restrict__ s,
                                                    float* __restrict__ d, int n4)
{
    const int i = blockIdx.x * 256 + threadIdx.x;
    if (i < n4) {
        float4 v = *(const float4*)(s + (size_t)i * 4);
        v.x = rtf32(v.x); v.y = rtf32(v.y); v.z = rtf32(v.z); v.w = rtf32(v.w);
        *(float4*)(d + (size_t)i * 4) = v;
    }
}

// ---------------- LayerNorm (tf32-rounded output) ----------------------------
__global__ __launch_bounds__(256) void ln_kernel(const float* __restrict__ x,
                                                 const float* __restrict__ g,
                                                 const float* __restrict__ be,
                                                 float* __restrict__ y)
{
    const int row = blockIdx.x;
    const int tid = threadIdx.x;
    const float* xr = x + (size_t)row * DD;

    float4 v0 = *(const float4*)&xr[tid * 4];
    float4 v1 = *(const float4*)&xr[1024 + tid * 4];

    float s  = v0.x + v0.y + v0.z + v0.w + v1.x + v1.y + v1.z + v1.w;
    float ss = v0.x*v0.x + v0.y*v0.y + v0.z*v0.z + v0.w*v0.w
             + v1.x*v1.x + v1.y*v1.y + v1.z*v1.z + v1.w*v1.w;

    #pragma unroll
    for (int o = 16; o > 0; o >>= 1) {
        s  += __shfl_xor_sync(0xffffffffu, s,  o);
        ss += __shfl_xor_sync(0xffffffffu, ss, o);
    }
    __shared__ float rs[8], rss[8];
    __shared__ float mean_s, rstd_s;
    const int w = tid >> 5, ln = tid & 31;
    if (ln == 0) { rs[w] = s; rss[w] = ss; }
    __syncthreads();
    if (tid == 0) {
        float S = 0.f, SSQ = 0.f;
        #pragma unroll
        for (int i = 0; i < 8; i++) { S += rs[i]; SSQ += rss[i]; }
        float mean = S * (1.0f / DD);
        float var  = SSQ * (1.0f / DD) - mean * mean;
        mean_s = mean;
        rstd_s = rsqrtf(var + 1e-5f);
    }
    __syncthreads();
    const float mean = mean_s, rstd = rstd_s;

    float4 g0  = *(const float4*)&g [tid * 4];
    float4 g1  = *(const float4*)&g [1024 + tid * 4];
    float4 b0  = *(const float4*)&be[tid * 4];
    float4 b1  = *(const float4*)&be[1024 + tid * 4];

    float4 o0, o1;
    o0.x = rtf32((v0.x - mean) * rstd * g0.x + b0.x);
    o0.y = rtf32((v0.y - mean) * rstd * g0.y + b0.y);
    o0.z = rtf32((v0.z - mean) * rstd * g0.z + b0.z);
    o0.w = rtf32((v0.w - mean) * rstd * g0.w + b0.w);
    o1.x = rtf32((v1.x - mean) * rstd * g1.x + b1.x);
    o1.y = rtf32((v1.y - mean) * rstd * g1.y + b1.y);
    o1.z = rtf32((v1.z - mean) * rstd * g1.z + b1.z);
    o1.w = rtf32((v1.w - mean) * rstd * g1.w + b1.w);

    float* yr = y + (size_t)row * DD;
    *(float4*)&yr[tid * 4]        = o0;
    *(float4*)&yr[1024 + tid * 4] = o1;
}

// ---------------- mma.sync tf32 GEMM -----------------------------------------
#define EPI_NONE       0
#define EPI_RESID      1
#define EPI_BIAS_GELU  2
#define EPI_BIAS_RESID 3
#define EPI_TF32       4   // plain store, rounded to tf32 (for qkv)

#define AS_STRIDE 36
#define BS_STRIDE 132
#define AS_BYTES  (128 * AS_STRIDE * 4)
#define BS_BYTES  (32 * BS_STRIDE * 4)
#define STAGE_BYTES (AS_BYTES + BS_BYTES)
#define GEMM_SMEM (2 * STAGE_BYTES)

template<int EPI>
__global__ __launch_bounds__(256, 2)
void mm_tf32(const float* __restrict__ A, const float* __restrict__ B,
             float* __restrict__ C, const float* __restrict__ bias,
             const float* __restrict__ resid, int M, int N, int K)
{
    extern __shared__ char dyn[];

    const int tid = threadIdx.x;
    const int wid = tid >> 5, lane = tid & 31;
    const int grp = lane >> 2, thr4 = lane & 3;
    const int wm = (wid & 1) * 64;
    const int wn = (wid >> 1) * 32;
    const int row0 = blockIdx.y * 128, col0 = blockIdx.x * 128;

    const float* Ab = A + (size_t)row0 * K;
    const float* Bb = B + col0;

    float acc[4][4][4];
    #pragma unroll
    for (int mi = 0; mi < 4; mi++)
        #pragma unroll
        for (int ni = 0; ni < 4; ni++)
            #pragma unroll
            for (int q = 0; q < 4; q++) acc[mi][ni][q] = 0.f;

    const int nk = K >> 5;

    auto load_stage = [&](int kt, int buf) {
        char* sb = dyn + buf * STAGE_BYTES;
        float* As = (float*)sb;
        float* Bs = (float*)(sb + AS_BYTES);
        const float* ga = Ab + (size_t)kt * 32;
        const float* gb = Bb + (size_t)kt * 32 * N;
        #pragma unroll
        for (int i = 0; i < 4; i++) {
            const int idx = tid + 256 * i;
            const int m = idx >> 3, k4 = idx & 7;
            cpasync16(&As[m * AS_STRIDE + k4 * 4], ga + (size_t)m * K + k4 * 4);
        }
        #pragma unroll
        for (int i = 0; i < 4; i++) {
            const int idx = tid + 256 * i;
            const int k = idx >> 5, n4 = idx & 31;
            cpasync16(&Bs[k * BS_STRIDE + n4 * 4], gb + (size_t)k * N + n4 * 4);
        }
        asm volatile("cp.async.commit_group;");
    };

    load_stage(0, 0);

    for (int kt = 0; kt < nk; kt++) {
        const int cur = kt & 1;
        if (kt + 1 < nk) {
            load_stage(kt + 1, cur ^ 1);
            asm volatile("cp.async.wait_group 1;");
        } else {
            asm volatile("cp.async.wait_group 0;");
        }
        __syncthreads();

        char* sb = dyn + cur * STAGE_BYTES;
        const float* As = (const float*)sb;
        const float* Bs = (const float*)(sb + AS_BYTES);

        #pragma unroll
        for (int kk = 0; kk < 32; kk += 8) {
            uint32_t afr[4][4], bfr[4][2];
            #pragma unroll
            for (int mi = 0; mi < 4; mi++) {
                const int m = wm + mi * 16 + grp;
                afr[mi][0] = __float_as_uint(As[m * AS_STRIDE + kk + thr4]);
                afr[mi][1] = __float_as_uint(As[(m + 8) * AS_STRIDE + kk + thr4]);
                afr[mi][2] = __float_as_uint(As[m * AS_STRIDE + kk + thr4 + 4]);
                afr[mi][3] = __float_as_uint(As[(m + 8) * AS_STRIDE + kk + thr4 + 4]);
            }
            #pragma unroll
            for (int ni = 0; ni < 4; ni++) {
                const int n = wn + ni * 8 + grp;
                bfr[ni][0] = __float_as_uint(Bs[(kk + thr4) * BS_STRIDE + n]);
                bfr[ni][1] = __float_as_uint(Bs[(kk + thr4 + 4) * BS_STRIDE + n]);
            }
            #pragma unroll
            for (int mi = 0; mi < 4; mi++)
                #pragma unroll
                for (int ni = 0; ni < 4; ni++)
                    mma_tf32(acc[mi][ni], afr[mi], bfr[ni]);
        }
        __syncthreads();
    }

    #pragma unroll
    for (int mi = 0; mi < 4; mi++) {
        #pragma unroll
        for (int half = 0; half < 2; half++) {
            const int r = row0 + wm + mi * 16 + grp + half * 8;
            #pragma unroll
            for (int ni = 0; ni < 4; ni++) {
                const int c = col0 + wn + ni * 8 + thr4 * 2;
                float v0 = acc[mi][ni][half * 2 + 0];
                float v1 = acc[mi][ni][half * 2 + 1];
                if (EPI == EPI_BIAS_GELU || EPI == EPI_BIAS_RESID) {
                    v0 += bias[c]; v1 += bias[c + 1];
                }
                if (EPI == EPI_RESID || EPI == EPI_BIAS_RESID) {
                    const float2 rr = *(const float2*)&resid[(size_t)r * N + c];
                    v0 += rr.x; v1 += rr.y;
                }
                if (EPI == EPI_BIAS_GELU) {
                    v0 = rtf32(0.5f * v0 * (1.0f + erff(v0 * 0.70710678118654752f)));
                    v1 = rtf32(0.5f * v1 * (1.0f + erff(v1 * 0.70710678118654752f)));
                }
                if (EPI == EPI_TF32) { v0 = rtf32(v0); v1 = rtf32(v1); }
                float2 o; o.x = v0; o.y = v1;
                *(float2*)&C[(size_t)r * N + c] = o;
            }
        }
    }
}

// ---------------- tensor-core flash attention -------------------------------
// Q tile 128 (8 warps x 16 rows), K tile 64. mask: key j allowed iff j <= q%1024.
#define QT 128
#define KT 64
#define QS_STR 132
#define KS_STR 132
#define VS_STR 136
#define PS_STR 68
#define ATTN_SMEM ((QT*QS_STR + KT*KS_STR + KT*VS_STR + QT*PS_STR) * 4)  // 171008

__global__ __launch_bounds__(256) void attn_mma(const float* __restrict__ qkv,
                                                float* __restrict__ out)
{
    extern __shared__ float sm[];
    float* Qs = sm;
    float* Ks = Qs + QT * QS_STR;
    float* Vs = Ks + KT * KS_STR;
    float* Ps = Vs + KT * VS_STR;

    const int tid = threadIdx.x;
    const int wid = tid >> 5, lane = tid & 31;
    const int grp = lane >> 2, thr4 = lane & 3;
    const int qt = blockIdx.x, bh = blockIdx.y;
    const int b = bh >> 4, h = bh & 15;
    const int q0 = qt * QT;
    const float scale = 0.08838834764831845f;

    // load Q tile (values already tf32-rounded by qkv epilogue)
    for (int i = tid; i < QT * 32; i += 256) {
        const int r = i >> 5, c4 = (i & 31) * 4;
        *(float4*)&Qs[r * QS_STR + c4] =
            *(const float4*)&qkv[(size_t)(b * SS + q0 + r) * QKVN + h * HD + c4];
    }

    const int r0 = wid * 16 + grp, r1 = r0 + 8;
    const int qmod0 = (q0 + r0) & (CHUNK - 1);
    const int qmod1 = (q0 + r1) & (CHUNK - 1);

    float O[16][4];
    #pragma unroll
    for (int nt = 0; nt < 16; nt++)
        #pragma unroll
        for (int q = 0; q < 4; q++) O[nt][q] = 0.f;
    float m0 = -1e30f, m1 = -1e30f, l0 = 0.f, l1 = 0.f;

    const int nkt = ((qt & 7) << 1) + 2;
    for (int kt = 0; kt < nkt; kt++) {
        const int kb = kt * KT;
        __syncthreads();
        for (int i = tid; i < KT * 32; i += 256) {
            const int r = i >> 5, c4 = (i & 31) * 4;
            const float* kp = &qkv[(size_t)(b * SS + kb + r) * QKVN + DD + h * HD + c4];
            *(float4*)&Ks[r * KS_STR + c4] = *(const float4*)kp;
            *(float4*)&Vs[r * VS_STR + c4] = *(const float4*)(kp + DD);
        }
        __syncthreads();

        // ---- S = Q K^T  (per warp: 16 rows x 64 keys) ----
        float Sa[8][4];
        #pragma unroll
        for (int nt = 0; nt < 8; nt++)
            #pragma unroll
            for (int q = 0; q < 4; q++) Sa[nt][q] = 0.f;

        #pragma unroll
        for (int kk = 0; kk < HD; kk += 8) {
            uint32_t a[4];
            a[0] = __float_as_uint(Qs[r0 * QS_STR + kk + thr4]);
            a[1] = __float_as_uint(Qs[r1 * QS_STR + kk + thr4]);
            a[2] = __float_as_uint(Qs[r0 * QS_STR + kk + thr4 + 4]);
            a[3] = __float_as_uint(Qs[r1 * QS_STR + kk + thr4 + 4]);
            #pragma unroll
            for (int nt = 0; nt < 8; nt++) {
                uint32_t bfr[2];
                bfr[0] = __float_as_uint(Ks[(nt * 8 + grp) * KS_STR + kk + thr4]);
                bfr[1] = __float_as_uint(Ks[(nt * 8 + grp) * KS_STR + kk + thr4 + 4]);
                mma_tf32(Sa[nt], a, bfr);
            }
        }

        // ---- softmax (online) ----
        float mt0 = -1e30f, mt1 = -1e30f;
        #pragma unroll
        for (int nt = 0; nt < 8; nt++) {
            #pragma unroll
            for (int c = 0; c < 2; c++) {
                const int j = kb + nt * 8 + 2 * thr4 + c;
                Sa[nt][c]     = (j <= qmod0) ? Sa[nt][c]     * scale : -1e30f;
                Sa[nt][c + 2] = (j <= qmod1) ? Sa[nt][c + 2] * scale : -1e30f;
                mt0 = fmaxf(mt0, Sa[nt][c]);
                mt1 = fmaxf(mt1, Sa[nt][c + 2]);
            }
        }
        mt0 = fmaxf(mt0, __shfl_xor_sync(0xffffffffu, mt0, 1));
        mt0 = fmaxf(mt0, __shfl_xor_sync(0xffffffffu, mt0, 2));
        mt1 = fmaxf(mt1, __shfl_xor_sync(0xffffffffu, mt1, 1));
        mt1 = fmaxf(mt1, __shfl_xor_sync(0xffffffffu, mt1, 2));

        const float mn0 = fmaxf(m0, mt0), mn1 = fmaxf(m1, mt1);
        const float al0 = __expf(m0 - mn0), al1 = __expf(m1 - mn1);
        #pragma unroll
        for (int nt = 0; nt < 16; nt++) {
            O[nt][0] *= al0; O[nt][1] *= al0;
            O[nt][2] *= al1; O[nt][3] *= al1;
        }

        float s0 = 0.f, s1 = 0.f;
        #pragma unroll
        for (int nt = 0; nt < 8; nt++) {
            #pragma unroll
            for (int c = 0; c < 2; c++) {
                const int col = nt * 8 + 2 * thr4 + c;
                float p0 = rtf32(__expf(Sa[nt][c]     - mn0));
                float p1 = rtf32(__expf(Sa[nt][c + 2] - mn1));
                s0 += p0; s1 += p1;
                Ps[r0 * PS_STR + col] = p0;
                Ps[r1 * PS_STR + col] = p1;
            }
        }
        s0 += __shfl_xor_sync(0xffffffffu, s0, 1);
        s0 += __shfl_xor_sync(0xffffffffu, s0, 2);
        s1 += __shfl_xor_sync(0xffffffffu, s1, 1);
        s1 += __shfl_xor_sync(0xffffffffu, s1, 2);
        l0 = l0 * al0 + s0;  m0 = mn0;
        l1 = l1 * al1 + s1;  m1 = mn1;
        __syncwarp();

        // ---- O += P @ V ----
        #pragma unroll
        for (int kk = 0; kk < KT; kk += 8) {
            uint32_t a[4];
            a[0] = __float_as_uint(Ps[r0 * PS_STR + kk + thr4]);
            a[1] = __float_as_uint(Ps[r1 * PS_STR + kk + thr4]);
            a[2] = __float_as_uint(Ps[r0 * PS_STR + kk + thr4 + 4]);
            a[3] = __float_as_uint(Ps[r1 * PS_STR + kk + thr4 + 4]);
            #pragma unroll
            for (int nt = 0; nt < 16; nt++) {
                uint32_t bfr[2];
                bfr[0] = __float_as_uint(Vs[(kk + thr4) * VS_STR + nt * 8 + grp]);
                bfr[1] = __float_as_uint(Vs[(kk + thr4 + 4) * VS_STR + nt * 8 + grp]);
                mma_tf32(O[nt], a, bfr);
            }
        }
    }

    const float i0 = 1.0f / l0, i1 = 1.0f / l1;
    #pragma unroll
    for (int nt = 0; nt < 16; nt++) {
        const int c = h * HD + nt * 8 + 2 * thr4;
        float2 o0, o1;
        o0.x = rtf32(O[nt][0] * i0); o0.y = rtf32(O[nt][1] * i0);
        o1.x = rtf32(O[nt][2] * i1); o1.y = rtf32(O[nt][3] * i1);
        *(float2*)&out[(size_t)(b * SS + q0 + r0) * DD + c] = o0;
        *(float2*)&out[(size_t)(b * SS + q0 + r1) * DD + c] = o1;
    }
}

// ---------------- launch ----------------------------------------------------
extern "C" void kernel_launch(void* const* d_in, const int* in_sizes, int n_in,
                              void* d_out, int out_size)
{
    const float* x     = (const float*)d_in[0];
    const float* w_qkv = (const float*)d_in[1];
    const float* w_o   = (const float*)d_in[2];
    const float* w1    = (const float*)d_in[3];
    const float* b1    = (const float*)d_in[4];
    const float* w2    = (const float*)d_in[5];
    const float* b2    = (const float*)d_in[6];
    const float* g1    = (const float*)d_in[7];
    const float* be1   = (const float*)d_in[8];
    const float* g2    = (const float*)d_in[9];
    const float* be2   = (const float*)d_in[10];
    float* out = (float*)d_out;

    float *p_ln, *p_qkv, *p_att, *p_x2, *p_act;
    float *p_wqkv, *p_wo, *p_w1, *p_w2;
    cudaGetSymbolAddress((void**)&p_ln,  g_ln);
    cudaGetSymbolAddress((void**)&p_qkv, g_qkv);
    cudaGetSymbolAddress((void**)&p_att, g_att);
    cudaGetSymbolAddress((void**)&p_x2,  g_x2);
    cudaGetSymbolAddress((void**)&p_act, g_act);
    cudaGetSymbolAddress((void**)&p_wqkv, g_wqkv_r);
    cudaGetSymbolAddress((void**)&p_wo,   g_wo_r);
    cudaGetSymbolAddress((void**)&p_w1,   g_w1_r);
    cudaGetSymbolAddress((void**)&p_w2,   g_w2_r);

    cudaFuncSetAttribute(attn_mma,
                         cudaFuncAttributeMaxDynamicSharedMemorySize, ATTN_SMEM);
    cudaFuncSetAttribute(mm_tf32<EPI_TF32>,
                         cudaFuncAttributeMaxDynamicSharedMemorySize, GEMM_SMEM);
    cudaFuncSetAttribute(mm_tf32<EPI_RESID>,
                         cudaFuncAttributeMaxDynamicSharedMemorySize, GEMM_SMEM);
    cudaFuncSetAttribute(mm_tf32<EPI_BIAS_GELU>,
                         cudaFuncAttributeMaxDynamicSharedMemorySize, GEMM_SMEM);
    cudaFuncSetAttribute(mm_tf32<EPI_BIAS_RESID>,
                         cudaFuncAttributeMaxDynamicSharedMemorySize, GEMM_SMEM);

    // 0) round weights to tf32 once
    round_kernel<<<(DD*QKVN/4 + 255)/256, 256>>>(w_qkv, p_wqkv, DD*QKVN/4);
    round_kernel<<<(DD*DD/4   + 255)/256, 256>>>(w_o,   p_wo,   DD*DD/4);
    round_kernel<<<(DD*FFN/4  + 255)/256, 256>>>(w1,    p_w1,   DD*FFN/4);
    round_kernel<<<(FFN*DD/4  + 255)/256, 256>>>(w2,    p_w2,   FFN*DD/4);

    // 1) LN1
    ln_kernel<<<ROWS, 256>>>(x, g1, be1, p_ln);

    // 2) qkv = ln1 @ w_qkv (tf32-rounded output for attention MMA)
    mm_tf32<EPI_TF32><<<dim3(QKVN/128, ROWS/128), 256, GEMM_SMEM>>>(
        p_ln, p_wqkv, p_qkv, nullptr, nullptr, ROWS, QKVN, DD);

    // 3) attention (tensor cores)
    attn_mma<<<dim3(SS/QT, BB*HH), 256, ATTN_SMEM>>>(p_qkv, p_att);

    // 4) x2 = attn_out @ w_o + x
    mm_tf32<EPI_RESID><<<dim3(DD/128, ROWS/128), 256, GEMM_SMEM>>>(
        p_att, p_wo, p_x2, nullptr, x, ROWS, DD, DD);

    // 5) LN2
    ln_kernel<<<ROWS, 256>>>(p_x2, g2, be2, p_ln);

    // 6) act = gelu(ln2 @ w1 + b1)
    mm_tf32<EPI_BIAS_GELU><<<dim3(FFN/128, ROWS/128), 256, GEMM_SMEM>>>(
        p_ln, p_w1, p_act, b1, nullptr, ROWS, FFN, DD);

    // 7) out = act @ w2 + b2 + x2
    mm_tf32<EPI_BIAS_RESID><<<dim3(DD/128, ROWS/128), 256, GEMM_SMEM>>>(
        p_act, p_w2, out, b2, p_x2, ROWS, DD, FFN);
}

// round 5
// speedup vs baseline: 4.7205x; 1.0697x over previous
#include <cuda_runtime.h>
#include <cuda_bf16.h>
#include <math.h>
#include <stdint.h>

// Problem constants
#define BB 2
#define SS 2048
#define DD 2048
#define HH 16
#define HD 128
#define CHUNK 1024
#define ROWS (BB*SS)          // 4096
#define QKVN (3*DD)           // 6144
#define FFN  (4*DD)           // 8192

// ---------------- scratch ----------------------------------------------------
__device__ float g_ln [(size_t)ROWS*DD];
__device__ float g_qkv[(size_t)ROWS*QKVN];
__device__ float g_att[(size_t)ROWS*DD];
__device__ float g_x2 [(size_t)ROWS*DD];
__device__ float g_act[(size_t)ROWS*FFN];
__device__ float g_wqkv_r[(size_t)DD*QKVN];
__device__ float g_wo_r [(size_t)DD*DD];
__device__ float g_w1_r [(size_t)DD*FFN];
__device__ float g_w2_r [(size_t)FFN*DD];

// ---------------- helpers ----------------------------------------------------
__device__ __forceinline__ float rtf32(float x) {
    uint32_t u;
    asm("cvt.rna.tf32.f32 %0, %1;" : "=r"(u) : "f"(x));
    return __uint_as_float(u);
}
__device__ __forceinline__ uint32_t s2u(const void* p) {
    uint32_t a;
    asm("{ .reg .u64 t; cvta.to.shared.u64 t, %1; cvt.u32.u64 %0, t; }"
        : "=r"(a) : "l"(p));
    return a;
}
__device__ __forceinline__ void cpasync16(void* s, const void* g) {
    asm volatile("cp.async.cg.shared.global [%0], [%1], 16;"
                 :: "r"(s2u(s)), "l"(g));
}
__device__ __forceinline__ void mma_tf32(float* c, const uint32_t* a, const uint32_t* b) {
    asm volatile(
        "mma.sync.aligned.m16n8k8.row.col.f32.tf32.tf32.f32 "
        "{%0,%1,%2,%3}, {%4,%5,%6,%7}, {%8,%9}, {%0,%1,%2,%3};"
        : "+f"(c[0]), "+f"(c[1]), "+f"(c[2]), "+f"(c[3])
        : "r"(a[0]), "r"(a[1]), "r"(a[2]), "r"(a[3]), "r"(b[0]), "r"(b[1]));
}
// tf32 A-fragment via b16 ldmatrix: one x4 loads the full m16k8 fragment.
__device__ __forceinline__ void ldsm_x4(uint32_t* r, uint32_t saddr) {
    asm volatile("ldmatrix.sync.aligned.m8n8.x4.shared.b16 {%0,%1,%2,%3}, [%4];"
                 : "=r"(r[0]), "=r"(r[1]), "=r"(r[2]), "=r"(r[3]) : "r"(saddr));
}

// ---------------- weight tf32 rounding ---------------------------------------
__global__ __launch_bounds__(256) void round_kernel(const float* __restrict__ s,
                                                    float* __restrict__ d, int n4)
{
    const int i = blockIdx.x * 256 + threadIdx.x;
    if (i < n4) {
        float4 v = *(const float4*)(s + (size_t)i * 4);
        v.x = rtf32(v.x); v.y = rtf32(v.y); v.z = rtf32(v.z); v.w = rtf32(v.w);
        *(float4*)(d + (size_t)i * 4) = v;
    }
}

// ---------------- LayerNorm (tf32-rounded output) ----------------------------
__global__ __launch_bounds__(256) void ln_kernel(const float* __restrict__ x,
                                                 const float* __restrict__ g,
                                                 const float* __restrict__ be,
                                                 float* __restrict__ y)
{
    const int row = blockIdx.x;
    const int tid = threadIdx.x;
    const float* xr = x + (size_t)row * DD;

    float4 v0 = *(const float4*)&xr[tid * 4];
    float4 v1 = *(const float4*)&xr[1024 + tid * 4];

    float s  = v0.x + v0.y + v0.z + v0.w + v1.x + v1.y + v1.z + v1.w;
    float ss = v0.x*v0.x + v0.y*v0.y + v0.z*v0.z + v0.w*v0.w
             + v1.x*v1.x + v1.y*v1.y + v1.z*v1.z + v1.w*v1.w;

    #pragma unroll
    for (int o = 16; o > 0; o >>= 1) {
        s  += __shfl_xor_sync(0xffffffffu, s,  o);
        ss += __shfl_xor_sync(0xffffffffu, ss, o);
    }
    __shared__ float rs[8], rss[8];
    __shared__ float mean_s, rstd_s;
    const int w = tid >> 5, ln = tid & 31;
    if (ln == 0) { rs[w] = s; rss[w] = ss; }
    __syncthreads();
    if (tid == 0) {
        float S = 0.f, SSQ = 0.f;
        #pragma unroll
        for (int i = 0; i < 8; i++) { S += rs[i]; SSQ += rss[i]; }
        float mean = S * (1.0f / DD);
        float var  = SSQ * (1.0f / DD) - mean * mean;
        mean_s = mean;
        rstd_s = rsqrtf(var + 1e-5f);
    }
    __syncthreads();
    const float mean = mean_s, rstd = rstd_s;

    float4 g0  = *(const float4*)&g [tid * 4];
    float4 g1  = *(const float4*)&g [1024 + tid * 4];
    float4 b0  = *(const float4*)&be[tid * 4];
    float4 b1  = *(const float4*)&be[1024 + tid * 4];

    float4 o0, o1;
    o0.x = rtf32((v0.x - mean) * rstd * g0.x + b0.x);
    o0.y = rtf32((v0.y - mean) * rstd * g0.y + b0.y);
    o0.z = rtf32((v0.z - mean) * rstd * g0.z + b0.z);
    o0.w = rtf32((v0.w - mean) * rstd * g0.w + b0.w);
    o1.x = rtf32((v1.x - mean) * rstd * g1.x + b1.x);
    o1.y = rtf32((v1.y - mean) * rstd * g1.y + b1.y);
    o1.z = rtf32((v1.z - mean) * rstd * g1.z + b1.z);
    o1.w = rtf32((v1.w - mean) * rstd * g1.w + b1.w);

    float* yr = y + (size_t)row * DD;
    *(float4*)&yr[tid * 4]        = o0;
    *(float4*)&yr[1024 + tid * 4] = o1;
}

// ---------------- mma.sync tf32 GEMM: 128x256 CTA tile, 64x64 warp tile ------
#define EPI_RESID      1
#define EPI_BIAS_GELU  2
#define EPI_BIAS_RESID 3
#define EPI_TF32       4

#define AS_STRIDE 36
#define BS_STRIDE 264                        // == 8 mod 32: conflict-free gather
#define AS_BYTES  (128 * AS_STRIDE * 4)      // 18432
#define BS_BYTES  (32 * BS_STRIDE * 4)       // 33792
#define STAGE_BYTES (AS_BYTES + BS_BYTES)    // 52224
#define GEMM_SMEM (2 * STAGE_BYTES)          // 104448

template<int EPI>
__global__ __launch_bounds__(256, 1)
void mm_tf32(const float* __restrict__ A, const float* __restrict__ B,
             float* __restrict__ C, const float* __restrict__ bias,
             const float* __restrict__ resid, int M, int N, int K)
{
    extern __shared__ char dyn[];

    const int tid = threadIdx.x;
    const int wid = tid >> 5, lane = tid & 31;
    const int grp = lane >> 2, thr4 = lane & 3;
    const int wm = (wid >> 2) * 64;          // 0 or 64
    const int wn = (wid & 3) * 64;           // 0,64,128,192
    const int row0 = blockIdx.y * 128, col0 = blockIdx.x * 256;

    // ldmatrix source row/k-offset for this lane (A fragment)
    const int lrow = (lane & 7) + ((lane >> 3) & 1) * 8;   // row within 16
    const int lkof = (lane >> 4) * 4;                      // 0 or 4

    const float* Ab = A + (size_t)row0 * K;
    const float* Bb = B + col0;

    float acc[4][8][4];
    #pragma unroll
    for (int mi = 0; mi < 4; mi++)
        #pragma unroll
        for (int ni = 0; ni < 8; ni++)
            #pragma unroll
            for (int q = 0; q < 4; q++) acc[mi][ni][q] = 0.f;

    const int nk = K >> 5;
    const uint32_t dynb = s2u(dyn);

    auto load_stage = [&](int kt, int buf) {
        char* sb = dyn + buf * STAGE_BYTES;
        float* As = (float*)sb;
        float* Bs = (float*)(sb + AS_BYTES);
        const float* ga = Ab + (size_t)kt * 32;
        const float* gb = Bb + (size_t)kt * 32 * N;
        #pragma unroll
        for (int i = 0; i < 4; i++) {                  // A: 1024 float4
            const int idx = tid + 256 * i;
            const int m = idx >> 3, k4 = idx & 7;
            cpasync16(&As[m * AS_STRIDE + k4 * 4], ga + (size_t)m * K + k4 * 4);
        }
        #pragma unroll
        for (int i = 0; i < 8; i++) {                  // B: 2048 float4
            const int idx = tid + 256 * i;
            const int k = idx >> 6, n4 = idx & 63;
            cpasync16(&Bs[k * BS_STRIDE + n4 * 4], gb + (size_t)k * N + n4 * 4);
        }
        asm volatile("cp.async.commit_group;");
    };

    load_stage(0, 0);

    for (int kt = 0; kt < nk; kt++) {
        const int cur = kt & 1;
        if (kt + 1 < nk) {
            load_stage(kt + 1, cur ^ 1);
            asm volatile("cp.async.wait_group 1;");
        } else {
            asm volatile("cp.async.wait_group 0;");
        }
        __syncthreads();

        const uint32_t as_b = dynb + cur * STAGE_BYTES;
        const float* Bs = (const float*)(dyn + cur * STAGE_BYTES + AS_BYTES);

        #pragma unroll
        for (int kk = 0; kk < 32; kk += 8) {
            uint32_t a[4][4];
            #pragma unroll
            for (int mi = 0; mi < 4; mi++) {
                const uint32_t addr = as_b +
                    (uint32_t)(((wm + mi * 16 + lrow) * AS_STRIDE + kk + lkof) * 4);
                ldsm_x4(a[mi], addr);
            }
            #pragma unroll
            for (int ni = 0; ni < 8; ni++) {
                const int n = wn + ni * 8 + grp;
                uint32_t bfr[2];
                bfr[0] = __float_as_uint(Bs[(kk + thr4) * BS_STRIDE + n]);
                bfr[1] = __float_as_uint(Bs[(kk + thr4 + 4) * BS_STRIDE + n]);
                #pragma unroll
                for (int mi = 0; mi < 4; mi++)
                    mma_tf32(acc[mi][ni], a[mi], bfr);
            }
        }
        __syncthreads();
    }

    // ---- epilogue ----
    #pragma unroll
    for (int mi = 0; mi < 4; mi++) {
        #pragma unroll
        for (int half = 0; half < 2; half++) {
            const int r = row0 + wm + mi * 16 + grp + half * 8;
            #pragma unroll
            for (int ni = 0; ni < 8; ni++) {
                const int c = col0 + wn + ni * 8 + thr4 * 2;
                float v0 = acc[mi][ni][half * 2 + 0];
                float v1 = acc[mi][ni][half * 2 + 1];
                if (EPI == EPI_BIAS_GELU || EPI == EPI_BIAS_RESID) {
                    v0 += bias[c]; v1 += bias[c + 1];
                }
                if (EPI == EPI_RESID || EPI == EPI_BIAS_RESID) {
                    const float2 rr = *(const float2*)&resid[(size_t)r * N + c];
                    v0 += rr.x; v1 += rr.y;
                }
                if (EPI == EPI_BIAS_GELU) {
                    v0 = rtf32(0.5f * v0 * (1.0f + erff(v0 * 0.70710678118654752f)));
                    v1 = rtf32(0.5f * v1 * (1.0f + erff(v1 * 0.70710678118654752f)));
                }
                if (EPI == EPI_TF32) { v0 = rtf32(v0); v1 = rtf32(v1); }
                float2 o; o.x = v0; o.y = v1;
                *(float2*)&C[(size_t)r * N + c] = o;
            }
        }
    }
}

// ---------------- tensor-core flash attention (unchanged) --------------------
#define QT 128
#define KT 64
#define QS_STR 132
#define KS_STR 132
#define VS_STR 136
#define PS_STR 68
#define ATTN_SMEM ((QT*QS_STR + KT*KS_STR + KT*VS_STR + QT*PS_STR) * 4)

__global__ __launch_bounds__(256) void attn_mma(const float* __restrict__ qkv,
                                                float* __restrict__ out)
{
    extern __shared__ float sm[];
    float* Qs = sm;
    float* Ks = Qs + QT * QS_STR;
    float* Vs = Ks + KT * KS_STR;
    float* Ps = Vs + KT * VS_STR;

    const int tid = threadIdx.x;
    const int wid = tid >> 5, lane = tid & 31;
    const int grp = lane >> 2, thr4 = lane & 3;
    const int qt = blockIdx.x, bh = blockIdx.y;
    const int b = bh >> 4, h = bh & 15;
    const int q0 = qt * QT;
    const float scale = 0.08838834764831845f;

    for (int i = tid; i < QT * 32; i += 256) {
        const int r = i >> 5, c4 = (i & 31) * 4;
        *(float4*)&Qs[r * QS_STR + c4] =
            *(const float4*)&qkv[(size_t)(b * SS + q0 + r) * QKVN + h * HD + c4];
    }

    const int r0 = wid * 16 + grp, r1 = r0 + 8;
    const int qmod0 = (q0 + r0) & (CHUNK - 1);
    const int qmod1 = (q0 + r1) & (CHUNK - 1);

    float O[16][4];
    #pragma unroll
    for (int nt = 0; nt < 16; nt++)
        #pragma unroll
        for (int q = 0; q < 4; q++) O[nt][q] = 0.f;
    float m0 = -1e30f, m1 = -1e30f, l0 = 0.f, l1 = 0.f;

    const int nkt = ((qt & 7) << 1) + 2;
    for (int kt = 0; kt < nkt; kt++) {
        const int kb = kt * KT;
        __syncthreads();
        for (int i = tid; i < KT * 32; i += 256) {
            const int r = i >> 5, c4 = (i & 31) * 4;
            const float* kp = &qkv[(size_t)(b * SS + kb + r) * QKVN + DD + h * HD + c4];
            *(float4*)&Ks[r * KS_STR + c4] = *(const float4*)kp;
            *(float4*)&Vs[r * VS_STR + c4] = *(const float4*)(kp + DD);
        }
        __syncthreads();

        float Sa[8][4];
        #pragma unroll
        for (int nt = 0; nt < 8; nt++)
            #pragma unroll
            for (int q = 0; q < 4; q++) Sa[nt][q] = 0.f;

        #pragma unroll
        for (int kk = 0; kk < HD; kk += 8) {
            uint32_t a[4];
            a[0] = __float_as_uint(Qs[r0 * QS_STR + kk + thr4]);
            a[1] = __float_as_uint(Qs[r1 * QS_STR + kk + thr4]);
            a[2] = __float_as_uint(Qs[r0 * QS_STR + kk + thr4 + 4]);
            a[3] = __float_as_uint(Qs[r1 * QS_STR + kk + thr4 + 4]);
            #pragma unroll
            for (int nt = 0; nt < 8; nt++) {
                uint32_t bfr[2];
                bfr[0] = __float_as_uint(Ks[(nt * 8 + grp) * KS_STR + kk + thr4]);
                bfr[1] = __float_as_uint(Ks[(nt * 8 + grp) * KS_STR + kk + thr4 + 4]);
                mma_tf32(Sa[nt], a, bfr);
            }
        }

        float mt0 = -1e30f, mt1 = -1e30f;
        #pragma unroll
        for (int nt = 0; nt < 8; nt++) {
            #pragma unroll
            for (int c = 0; c < 2; c++) {
                const int j = kb + nt * 8 + 2 * thr4 + c;
                Sa[nt][c]     = (j <= qmod0) ? Sa[nt][c]     * scale : -1e30f;
                Sa[nt][c + 2] = (j <= qmod1) ? Sa[nt][c + 2] * scale : -1e30f;
                mt0 = fmaxf(mt0, Sa[nt][c]);
                mt1 = fmaxf(mt1, Sa[nt][c + 2]);
            }
        }
        mt0 = fmaxf(mt0, __shfl_xor_sync(0xffffffffu, mt0, 1));
        mt0 = fmaxf(mt0, __shfl_xor_sync(0xffffffffu, mt0, 2));
        mt1 = fmaxf(mt1, __shfl_xor_sync(0xffffffffu, mt1, 1));
        mt1 = fmaxf(mt1, __shfl_xor_sync(0xffffffffu, mt1, 2));

        const float mn0 = fmaxf(m0, mt0), mn1 = fmaxf(m1, mt1);
        const float al0 = __expf(m0 - mn0), al1 = __expf(m1 - mn1);
        #pragma unroll
        for (int nt = 0; nt < 16; nt++) {
            O[nt][0] *= al0; O[nt][1] *= al0;
            O[nt][2] *= al1; O[nt][3] *= al1;
        }

        float s0 = 0.f, s1 = 0.f;
        #pragma unroll
        for (int nt = 0; nt < 8; nt++) {
            #pragma unroll
            for (int c = 0; c < 2; c++) {
                const int col = nt * 8 + 2 * thr4 + c;
                float p0 = rtf32(__expf(Sa[nt][c]     - mn0));
                float p1 = rtf32(__expf(Sa[nt][c + 2] - mn1));
                s0 += p0; s1 += p1;
                Ps[r0 * PS_STR + col] = p0;
                Ps[r1 * PS_STR + col] = p1;
            }
        }
        s0 += __shfl_xor_sync(0xffffffffu, s0, 1);
        s0 += __shfl_xor_sync(0xffffffffu, s0, 2);
        s1 += __shfl_xor_sync(0xffffffffu, s1, 1);
        s1 += __shfl_xor_sync(0xffffffffu, s1, 2);
        l0 = l0 * al0 + s0;  m0 = mn0;
        l1 = l1 * al1 + s1;  m1 = mn1;
        __syncwarp();

        #pragma unroll
        for (int kk = 0; kk < KT; kk += 8) {
            uint32_t a[4];
            a[0] = __float_as_uint(Ps[r0 * PS_STR + kk + thr4]);
            a[1] = __float_as_uint(Ps[r1 * PS_STR + kk + thr4]);
            a[2] = __float_as_uint(Ps[r0 * PS_STR + kk + thr4 + 4]);
            a[3] = __float_as_uint(Ps[r1 * PS_STR + kk + thr4 + 4]);
            #pragma unroll
            for (int nt = 0; nt < 16; nt++) {
                uint32_t bfr[2];
                bfr[0] = __float_as_uint(Vs[(kk + thr4) * VS_STR + nt * 8 + grp]);
                bfr[1] = __float_as_uint(Vs[(kk + thr4 + 4) * VS_STR + nt * 8 + grp]);
                mma_tf32(O[nt], a, bfr);
            }
        }
    }

    const float i0 = 1.0f / l0, i1 = 1.0f / l1;
    #pragma unroll
    for (int nt = 0; nt < 16; nt++) {
        const int c = h * HD + nt * 8 + 2 * thr4;
        float2 o0, o1;
        o0.x = rtf32(O[nt][0] * i0); o0.y = rtf32(O[nt][1] * i0);
        o1.x = rtf32(O[nt][2] * i1); o1.y = rtf32(O[nt][3] * i1);
        *(float2*)&out[(size_t)(b * SS + q0 + r0) * DD + c] = o0;
        *(float2*)&out[(size_t)(b * SS + q0 + r1) * DD + c] = o1;
    }
}

// ---------------- launch ----------------------------------------------------
extern "C" void kernel_launch(void* const* d_in, const int* in_sizes, int n_in,
                              void* d_out, int out_size)
{
    const float* x     = (const float*)d_in[0];
    const float* w_qkv = (const float*)d_in[1];
    const float* w_o   = (const float*)d_in[2];
    const float* w1    = (const float*)d_in[3];
    const float* b1    = (const float*)d_in[4];
    const float* w2    = (const float*)d_in[5];
    const float* b2    = (const float*)d_in[6];
    const float* g1    = (const float*)d_in[7];
    const float* be1   = (const float*)d_in[8];
    const float* g2    = (const float*)d_in[9];
    const float* be2   = (const float*)d_in[10];
    float* out = (float*)d_out;

    float *p_ln, *p_qkv, *p_att, *p_x2, *p_act;
    float *p_wqkv, *p_wo, *p_w1, *p_w2;
    cudaGetSymbolAddress((void**)&p_ln,  g_ln);
    cudaGetSymbolAddress((void**)&p_qkv, g_qkv);
    cudaGetSymbolAddress((void**)&p_att, g_att);
    cudaGetSymbolAddress((void**)&p_x2,  g_x2);
    cudaGetSymbolAddress((void**)&p_act, g_act);
    cudaGetSymbolAddress((void**)&p_wqkv, g_wqkv_r);
    cudaGetSymbolAddress((void**)&p_wo,   g_wo_r);
    cudaGetSymbolAddress((void**)&p_w1,   g_w1_r);
    cudaGetSymbolAddress((void**)&p_w2,   g_w2_r);

    cudaFuncSetAttribute(attn_mma,
                         cudaFuncAttributeMaxDynamicSharedMemorySize, ATTN_SMEM);
    cudaFuncSetAttribute(mm_tf32<EPI_TF32>,
                         cudaFuncAttributeMaxDynamicSharedMemorySize, GEMM_SMEM);
    cudaFuncSetAttribute(mm_tf32<EPI_RESID>,
                         cudaFuncAttributeMaxDynamicSharedMemorySize, GEMM_SMEM);
    cudaFuncSetAttribute(mm_tf32<EPI_BIAS_GELU>,
                         cudaFuncAttributeMaxDynamicSharedMemorySize, GEMM_SMEM);
    cudaFuncSetAttribute(mm_tf32<EPI_BIAS_RESID>,
                         cudaFuncAttributeMaxDynamicSharedMemorySize, GEMM_SMEM);

    round_kernel<<<(DD*QKVN/4 + 255)/256, 256>>>(w_qkv, p_wqkv, DD*QKVN/4);
    round_kernel<<<(DD*DD/4   + 255)/256, 256>>>(w_o,   p_wo,   DD*DD/4);
    round_kernel<<<(DD*FFN/4  + 255)/256, 256>>>(w1,    p_w1,   DD*FFN/4);
    round_kernel<<<(FFN*DD/4  + 255)/256, 256>>>(w2,    p_w2,   FFN*DD/4);

    ln_kernel<<<ROWS, 256>>>(x, g1, be1, p_ln);

    mm_tf32<EPI_TF32><<<dim3(QKVN/256, ROWS/128), 256, GEMM_SMEM>>>(
        p_ln, p_wqkv, p_qkv, nullptr, nullptr, ROWS, QKVN, DD);

    attn_mma<<<dim3(SS/QT, BB*HH), 256, ATTN_SMEM>>>(p_qkv, p_att);

    mm_tf32<EPI_RESID><<<dim3(DD/256, ROWS/128), 256, GEMM_SMEM>>>(
        p_att, p_wo, p_x2, nullptr, x, ROWS, DD, DD);

    ln_kernel<<<ROWS, 256>>>(p_x2, g2, be2, p_ln);

    mm_tf32<EPI_BIAS_GELU><<<dim3(FFN/256, ROWS/128), 256, GEMM_SMEM>>>(
        p_ln, p_w1, p_act, b1, nullptr, ROWS, FFN, DD);

    mm_tf32<EPI_BIAS_RESID><<<dim3(DD/256, ROWS/128), 256, GEMM_SMEM>>>(
        p_act, p_w2, out, b2, p_x2, ROWS, DD, FFN);
}

// round 6
// speedup vs baseline: 4.9299x; 1.0444x over previous
#include <cuda_runtime.h>
#include <cuda_bf16.h>
#include <math.h>
#include <stdint.h>

// Problem constants
#define BB 2
#define SS 2048
#define DD 2048
#define HH 16
#define HD 128
#define CHUNK 1024
#define ROWS (BB*SS)          // 4096
#define QKVN (3*DD)           // 6144
#define FFN  (4*DD)           // 8192

// ---------------- scratch ----------------------------------------------------
__device__ float g_ln [(size_t)ROWS*DD];
__device__ float g_qkv[(size_t)ROWS*QKVN];
__device__ float g_att[(size_t)ROWS*DD];
__device__ float g_x2 [(size_t)ROWS*DD];
__device__ float g_act[(size_t)ROWS*FFN];
__device__ float g_wqkv_r[(size_t)DD*QKVN];
__device__ float g_wo_r [(size_t)DD*DD];
__device__ float g_w1_r [(size_t)DD*FFN];
__device__ float g_w2_r [(size_t)FFN*DD];

// ---------------- helpers ----------------------------------------------------
__device__ __forceinline__ float rtf32(float x) {
    uint32_t u;
    asm("cvt.rna.tf32.f32 %0, %1;" : "=r"(u) : "f"(x));
    return __uint_as_float(u);
}
__device__ __forceinline__ uint32_t s2u(const void* p) {
    uint32_t a;
    asm("{ .reg .u64 t; cvta.to.shared.u64 t, %1; cvt.u32.u64 %0, t; }"
        : "=r"(a) : "l"(p));
    return a;
}
__device__ __forceinline__ void cpasync16(void* s, const void* g) {
    asm volatile("cp.async.cg.shared.global [%0], [%1], 16;"
                 :: "r"(s2u(s)), "l"(g));
}
__device__ __forceinline__ void mma_tf32(float* c, const uint32_t* a, const uint32_t* b) {
    asm volatile(
        "mma.sync.aligned.m16n8k8.row.col.f32.tf32.tf32.f32 "
        "{%0,%1,%2,%3}, {%4,%5,%6,%7}, {%8,%9}, {%0,%1,%2,%3};"
        : "+f"(c[0]), "+f"(c[1]), "+f"(c[2]), "+f"(c[3])
        : "r"(a[0]), "r"(a[1]), "r"(a[2]), "r"(a[3]), "r"(b[0]), "r"(b[1]));
}
__device__ __forceinline__ void ldsm_x4(uint32_t* r, uint32_t saddr) {
    asm volatile("ldmatrix.sync.aligned.m8n8.x4.shared.b16 {%0,%1,%2,%3}, [%4];"
                 : "=r"(r[0]), "=r"(r[1]), "=r"(r[2]), "=r"(r[3]) : "r"(saddr));
}

// ---------------- weight tf32 rounding ---------------------------------------
__global__ __launch_bounds__(256) void round_kernel(const float* __restrict__ s,
                                                    float* __restrict__ d, int n4)
{
    const int i = blockIdx.x * 256 + threadIdx.x;
    if (i < n4) {
        float4 v = *(const float4*)(s + (size_t)i * 4);
        v.x = rtf32(v.x); v.y = rtf32(v.y); v.z = rtf32(v.z); v.w = rtf32(v.w);
        *(float4*)(d + (size_t)i * 4) = v;
    }
}

// ---------------- LayerNorm (tf32-rounded output) ----------------------------
__global__ __launch_bounds__(256) void ln_kernel(const float* __restrict__ x,
                                                 const float* __restrict__ g,
                                                 const float* __restrict__ be,
                                                 float* __restrict__ y)
{
    const int row = blockIdx.x;
    const int tid = threadIdx.x;
    const float* xr = x + (size_t)row * DD;

    float4 v0 = *(const float4*)&xr[tid * 4];
    float4 v1 = *(const float4*)&xr[1024 + tid * 4];

    float s  = v0.x + v0.y + v0.z + v0.w + v1.x + v1.y + v1.z + v1.w;
    float ss = v0.x*v0.x + v0.y*v0.y + v0.z*v0.z + v0.w*v0.w
             + v1.x*v1.x + v1.y*v1.y + v1.z*v1.z + v1.w*v1.w;

    #pragma unroll
    for (int o = 16; o > 0; o >>= 1) {
        s  += __shfl_xor_sync(0xffffffffu, s,  o);
        ss += __shfl_xor_sync(0xffffffffu, ss, o);
    }
    __shared__ float rs[8], rss[8];
    __shared__ float mean_s, rstd_s;
    const int w = tid >> 5, ln = tid & 31;
    if (ln == 0) { rs[w] = s; rss[w] = ss; }
    __syncthreads();
    if (tid == 0) {
        float S = 0.f, SSQ = 0.f;
        #pragma unroll
        for (int i = 0; i < 8; i++) { S += rs[i]; SSQ += rss[i]; }
        float mean = S * (1.0f / DD);
        float var  = SSQ * (1.0f / DD) - mean * mean;
        mean_s = mean;
        rstd_s = rsqrtf(var + 1e-5f);
    }
    __syncthreads();
    const float mean = mean_s, rstd = rstd_s;

    float4 g0  = *(const float4*)&g [tid * 4];
    float4 g1  = *(const float4*)&g [1024 + tid * 4];
    float4 b0  = *(const float4*)&be[tid * 4];
    float4 b1  = *(const float4*)&be[1024 + tid * 4];

    float4 o0, o1;
    o0.x = rtf32((v0.x - mean) * rstd * g0.x + b0.x);
    o0.y = rtf32((v0.y - mean) * rstd * g0.y + b0.y);
    o0.z = rtf32((v0.z - mean) * rstd * g0.z + b0.z);
    o0.w = rtf32((v0.w - mean) * rstd * g0.w + b0.w);
    o1.x = rtf32((v1.x - mean) * rstd * g1.x + b1.x);
    o1.y = rtf32((v1.y - mean) * rstd * g1.y + b1.y);
    o1.z = rtf32((v1.z - mean) * rstd * g1.z + b1.z);
    o1.w = rtf32((v1.w - mean) * rstd * g1.w + b1.w);

    float* yr = y + (size_t)row * DD;
    *(float4*)&yr[tid * 4]        = o0;
    *(float4*)&yr[1024 + tid * 4] = o1;
}

// ---------------- mma.sync tf32 GEMM: 128x256 CTA, grid (M-tiles, N-tiles) ---
// blockIdx.x = M tile (fast-varying) so a wave covers ALL M-tiles of a few
// N-columns -> each weight column strip is read once from DRAM per GEMM.
#define EPI_RESID      1
#define EPI_BIAS_GELU  2
#define EPI_BIAS_RESID 3
#define EPI_TF32       4

#define AS_STRIDE 36
#define BS_STRIDE 264
#define AS_BYTES  (128 * AS_STRIDE * 4)      // 18432
#define BS_BYTES  (32 * BS_STRIDE * 4)       // 33792
#define STAGE_BYTES (AS_BYTES + BS_BYTES)    // 52224
#define NSTAGE 3
#define GEMM_SMEM (NSTAGE * STAGE_BYTES)     // 156672

template<int EPI>
__global__ __launch_bounds__(256, 1)
void mm_tf32(const float* __restrict__ A, const float* __restrict__ B,
             float* __restrict__ C, const float* __restrict__ bias,
             const float* __restrict__ resid, int M, int N, int K)
{
    extern __shared__ char dyn[];

    const int tid = threadIdx.x;
    const int wid = tid >> 5, lane = tid & 31;
    const int grp = lane >> 2, thr4 = lane & 3;
    const int wm = (wid >> 2) * 64;
    const int wn = (wid & 3) * 64;
    const int row0 = blockIdx.x * 128, col0 = blockIdx.y * 256;

    const int lrow = (lane & 7) + ((lane >> 3) & 1) * 8;
    const int lkof = (lane >> 4) * 4;

    const float* Ab = A + (size_t)row0 * K;
    const float* Bb = B + col0;

    float acc[4][8][4];
    #pragma unroll
    for (int mi = 0; mi < 4; mi++)
        #pragma unroll
        for (int ni = 0; ni < 8; ni++)
            #pragma unroll
            for (int q = 0; q < 4; q++) acc[mi][ni][q] = 0.f;

    const int nk = K >> 5;
    const uint32_t dynb = s2u(dyn);

    auto load_stage = [&](int kt, int buf) {
        char* sb = dyn + buf * STAGE_BYTES;
        float* As = (float*)sb;
        float* Bs = (float*)(sb + AS_BYTES);
        const float* ga = Ab + (size_t)kt * 32;
        const float* gb = Bb + (size_t)kt * 32 * N;
        #pragma unroll
        for (int i = 0; i < 4; i++) {
            const int idx = tid + 256 * i;
            const int m = idx >> 3, k4 = idx & 7;
            cpasync16(&As[m * AS_STRIDE + k4 * 4], ga + (size_t)m * K + k4 * 4);
        }
        #pragma unroll
        for (int i = 0; i < 8; i++) {
            const int idx = tid + 256 * i;
            const int k = idx >> 6, n4 = idx & 63;
            cpasync16(&Bs[k * BS_STRIDE + n4 * 4], gb + (size_t)k * N + n4 * 4);
        }
        asm volatile("cp.async.commit_group;");
    };

    load_stage(0, 0);
    load_stage(1, 1);

    for (int kt = 0; kt < nk; kt++) {
        if (kt == nk - 1) asm volatile("cp.async.wait_group 0;");
        else              asm volatile("cp.async.wait_group 1;");
        __syncthreads();

        if (kt + 2 < nk) load_stage(kt + 2, (kt + 2) % NSTAGE);

        const int cur = kt % NSTAGE;
        const uint32_t as_b = dynb + cur * STAGE_BYTES;
        const float* Bs = (const float*)(dyn + cur * STAGE_BYTES + AS_BYTES);

        #pragma unroll
        for (int kk = 0; kk < 32; kk += 8) {
            uint32_t a[4][4];
            #pragma unroll
            for (int mi = 0; mi < 4; mi++) {
                const uint32_t addr = as_b +
                    (uint32_t)(((wm + mi * 16 + lrow) * AS_STRIDE + kk + lkof) * 4);
                ldsm_x4(a[mi], addr);
            }
            #pragma unroll
            for (int ni = 0; ni < 8; ni++) {
                const int n = wn + ni * 8 + grp;
                uint32_t bfr[2];
                bfr[0] = __float_as_uint(Bs[(kk + thr4) * BS_STRIDE + n]);
                bfr[1] = __float_as_uint(Bs[(kk + thr4 + 4) * BS_STRIDE + n]);
                #pragma unroll
                for (int mi = 0; mi < 4; mi++)
                    mma_tf32(acc[mi][ni], a[mi], bfr);
            }
        }
        __syncthreads();
    }

    // ---- epilogue ----
    #pragma unroll
    for (int mi = 0; mi < 4; mi++) {
        #pragma unroll
        for (int half = 0; half < 2; half++) {
            const int r = row0 + wm + mi * 16 + grp + half * 8;
            #pragma unroll
            for (int ni = 0; ni < 8; ni++) {
                const int c = col0 + wn + ni * 8 + thr4 * 2;
                float v0 = acc[mi][ni][half * 2 + 0];
                float v1 = acc[mi][ni][half * 2 + 1];
                if (EPI == EPI_BIAS_GELU || EPI == EPI_BIAS_RESID) {
                    v0 += bias[c]; v1 += bias[c + 1];
                }
                if (EPI == EPI_RESID || EPI == EPI_BIAS_RESID) {
                    const float2 rr = *(const float2*)&resid[(size_t)r * N + c];
                    v0 += rr.x; v1 += rr.y;
                }
                if (EPI == EPI_BIAS_GELU) {
                    v0 = rtf32(0.5f * v0 * (1.0f + erff(v0 * 0.70710678118654752f)));
                    v1 = rtf32(0.5f * v1 * (1.0f + erff(v1 * 0.70710678118654752f)));
                }
                if (EPI == EPI_TF32) { v0 = rtf32(v0); v1 = rtf32(v1); }
                float2 o; o.x = v0; o.y = v1;
                *(float2*)&C[(size_t)r * N + c] = o;
            }
        }
    }
}

// ---------------- tensor-core flash attention (unchanged) --------------------
#define QT 128
#define KT 64
#define QS_STR 132
#define KS_STR 132
#define VS_STR 136
#define PS_STR 68
#define ATTN_SMEM ((QT*QS_STR + KT*KS_STR + KT*VS_STR + QT*PS_STR) * 4)

__global__ __launch_bounds__(256) void attn_mma(const float* __restrict__ qkv,
                                                float* __restrict__ out)
{
    extern __shared__ float sm[];
    float* Qs = sm;
    float* Ks = Qs + QT * QS_STR;
    float* Vs = Ks + KT * KS_STR;
    float* Ps = Vs + KT * VS_STR;

    const int tid = threadIdx.x;
    const int wid = tid >> 5, lane = tid & 31;
    const int grp = lane >> 2, thr4 = lane & 3;
    const int qt = blockIdx.x, bh = blockIdx.y;
    const int b = bh >> 4, h = bh & 15;
    const int q0 = qt * QT;
    const float scale = 0.08838834764831845f;

    for (int i = tid; i < QT * 32; i += 256) {
        const int r = i >> 5, c4 = (i & 31) * 4;
        *(float4*)&Qs[r * QS_STR + c4] =
            *(const float4*)&qkv[(size_t)(b * SS + q0 + r) * QKVN + h * HD + c4];
    }

    const int r0 = wid * 16 + grp, r1 = r0 + 8;
    const int qmod0 = (q0 + r0) & (CHUNK - 1);
    const int qmod1 = (q0 + r1) & (CHUNK - 1);

    float O[16][4];
    #pragma unroll
    for (int nt = 0; nt < 16; nt++)
        #pragma unroll
        for (int q = 0; q < 4; q++) O[nt][q] = 0.f;
    float m0 = -1e30f, m1 = -1e30f, l0 = 0.f, l1 = 0.f;

    const int nkt = ((qt & 7) << 1) + 2;
    for (int kt = 0; kt < nkt; kt++) {
        const int kb = kt * KT;
        __syncthreads();
        for (int i = tid; i < KT * 32; i += 256) {
            const int r = i >> 5, c4 = (i & 31) * 4;
            const float* kp = &qkv[(size_t)(b * SS + kb + r) * QKVN + DD + h * HD + c4];
            *(float4*)&Ks[r * KS_STR + c4] = *(const float4*)kp;
            *(float4*)&Vs[r * VS_STR + c4] = *(const float4*)(kp + DD);
        }
        __syncthreads();

        float Sa[8][4];
        #pragma unroll
        for (int nt = 0; nt < 8; nt++)
            #pragma unroll
            for (int q = 0; q < 4; q++) Sa[nt][q] = 0.f;

        #pragma unroll
        for (int kk = 0; kk < HD; kk += 8) {
            uint32_t a[4];
            a[0] = __float_as_uint(Qs[r0 * QS_STR + kk + thr4]);
            a[1] = __float_as_uint(Qs[r1 * QS_STR + kk + thr4]);
            a[2] = __float_as_uint(Qs[r0 * QS_STR + kk + thr4 + 4]);
            a[3] = __float_as_uint(Qs[r1 * QS_STR + kk + thr4 + 4]);
            #pragma unroll
            for (int nt = 0; nt < 8; nt++) {
                uint32_t bfr[2];
                bfr[0] = __float_as_uint(Ks[(nt * 8 + grp) * KS_STR + kk + thr4]);
                bfr[1] = __float_as_uint(Ks[(nt * 8 + grp) * KS_STR + kk + thr4 + 4]);
                mma_tf32(Sa[nt], a, bfr);
            }
        }

        float mt0 = -1e30f, mt1 = -1e30f;
        #pragma unroll
        for (int nt = 0; nt < 8; nt++) {
            #pragma unroll
            for (int c = 0; c < 2; c++) {
                const int j = kb + nt * 8 + 2 * thr4 + c;
                Sa[nt][c]     = (j <= qmod0) ? Sa[nt][c]     * scale : -1e30f;
                Sa[nt][c + 2] = (j <= qmod1) ? Sa[nt][c + 2] * scale : -1e30f;
                mt0 = fmaxf(mt0, Sa[nt][c]);
                mt1 = fmaxf(mt1, Sa[nt][c + 2]);
            }
        }
        mt0 = fmaxf(mt0, __shfl_xor_sync(0xffffffffu, mt0, 1));
        mt0 = fmaxf(mt0, __shfl_xor_sync(0xffffffffu, mt0, 2));
        mt1 = fmaxf(mt1, __shfl_xor_sync(0xffffffffu, mt1, 1));
        mt1 = fmaxf(mt1, __shfl_xor_sync(0xffffffffu, mt1, 2));

        const float mn0 = fmaxf(m0, mt0), mn1 = fmaxf(m1, mt1);
        const float al0 = __expf(m0 - mn0), al1 = __expf(m1 - mn1);
        #pragma unroll
        for (int nt = 0; nt < 16; nt++) {
            O[nt][0] *= al0; O[nt][1] *= al0;
            O[nt][2] *= al1; O[nt][3] *= al1;
        }

        float s0 = 0.f, s1 = 0.f;
        #pragma unroll
        for (int nt = 0; nt < 8; nt++) {
            #pragma unroll
            for (int c = 0; c < 2; c++) {
                const int col = nt * 8 + 2 * thr4 + c;
                float p0 = rtf32(__expf(Sa[nt][c]     - mn0));
                float p1 = rtf32(__expf(Sa[nt][c + 2] - mn1));
                s0 += p0; s1 += p1;
                Ps[r0 * PS_STR + col] = p0;
                Ps[r1 * PS_STR + col] = p1;
            }
        }
        s0 += __shfl_xor_sync(0xffffffffu, s0, 1);
        s0 += __shfl_xor_sync(0xffffffffu, s0, 2);
        s1 += __shfl_xor_sync(0xffffffffu, s1, 1);
        s1 += __shfl_xor_sync(0xffffffffu, s1, 2);
        l0 = l0 * al0 + s0;  m0 = mn0;
        l1 = l1 * al1 + s1;  m1 = mn1;
        __syncwarp();

        #pragma unroll
        for (int kk = 0; kk < KT; kk += 8) {
            uint32_t a[4];
            a[0] = __float_as_uint(Ps[r0 * PS_STR + kk + thr4]);
            a[1] = __float_as_uint(Ps[r1 * PS_STR + kk + thr4]);
            a[2] = __float_as_uint(Ps[r0 * PS_STR + kk + thr4 + 4]);
            a[3] = __float_as_uint(Ps[r1 * PS_STR + kk + thr4 + 4]);
            #pragma unroll
            for (int nt = 0; nt < 16; nt++) {
                uint32_t bfr[2];
                bfr[0] = __float_as_uint(Vs[(kk + thr4) * VS_STR + nt * 8 + grp]);
                bfr[1] = __float_as_uint(Vs[(kk + thr4 + 4) * VS_STR + nt * 8 + grp]);
                mma_tf32(O[nt], a, bfr);
            }
        }
    }

    const float i0 = 1.0f / l0, i1 = 1.0f / l1;
    #pragma unroll
    for (int nt = 0; nt < 16; nt++) {
        const int c = h * HD + nt * 8 + 2 * thr4;
        float2 o0, o1;
        o0.x = rtf32(O[nt][0] * i0); o0.y = rtf32(O[nt][1] * i0);
        o1.x = rtf32(O[nt][2] * i1); o1.y = rtf32(O[nt][3] * i1);
        *(float2*)&out[(size_t)(b * SS + q0 + r0) * DD + c] = o0;
        *(float2*)&out[(size_t)(b * SS + q0 + r1) * DD + c] = o1;
    }
}

// ---------------- launch ----------------------------------------------------
extern "C" void kernel_launch(void* const* d_in, const int* in_sizes, int n_in,
                              void* d_out, int out_size)
{
    const float* x     = (const float*)d_in[0];
    const float* w_qkv = (const float*)d_in[1];
    const float* w_o   = (const float*)d_in[2];
    const float* w1    = (const float*)d_in[3];
    const float* b1    = (const float*)d_in[4];
    const float* w2    = (const float*)d_in[5];
    const float* b2    = (const float*)d_in[6];
    const float* g1    = (const float*)d_in[7];
    const float* be1   = (const float*)d_in[8];
    const float* g2    = (const float*)d_in[9];
    const float* be2   = (const float*)d_in[10];
    float* out = (float*)d_out;

    float *p_ln, *p_qkv, *p_att, *p_x2, *p_act;
    float *p_wqkv, *p_wo, *p_w1, *p_w2;
    cudaGetSymbolAddress((void**)&p_ln,  g_ln);
    cudaGetSymbolAddress((void**)&p_qkv, g_qkv);
    cudaGetSymbolAddress((void**)&p_att, g_att);
    cudaGetSymbolAddress((void**)&p_x2,  g_x2);
    cudaGetSymbolAddress((void**)&p_act, g_act);
    cudaGetSymbolAddress((void**)&p_wqkv, g_wqkv_r);
    cudaGetSymbolAddress((void**)&p_wo,   g_wo_r);
    cudaGetSymbolAddress((void**)&p_w1,   g_w1_r);
    cudaGetSymbolAddress((void**)&p_w2,   g_w2_r);

    cudaFuncSetAttribute(attn_mma,
                         cudaFuncAttributeMaxDynamicSharedMemorySize, ATTN_SMEM);
    cudaFuncSetAttribute(mm_tf32<EPI_TF32>,
                         cudaFuncAttributeMaxDynamicSharedMemorySize, GEMM_SMEM);
    cudaFuncSetAttribute(mm_tf32<EPI_RESID>,
                         cudaFuncAttributeMaxDynamicSharedMemorySize, GEMM_SMEM);
    cudaFuncSetAttribute(mm_tf32<EPI_BIAS_GELU>,
                         cudaFuncAttributeMaxDynamicSharedMemorySize, GEMM_SMEM);
    cudaFuncSetAttribute(mm_tf32<EPI_BIAS_RESID>,
                         cudaFuncAttributeMaxDynamicSharedMemorySize, GEMM_SMEM);

    round_kernel<<<(DD*QKVN/4 + 255)/256, 256>>>(w_qkv, p_wqkv, DD*QKVN/4);
    round_kernel<<<(DD*DD/4   + 255)/256, 256>>>(w_o,   p_wo,   DD*DD/4);
    round_kernel<<<(DD*FFN/4  + 255)/256, 256>>>(w1,    p_w1,   DD*FFN/4);
    round_kernel<<<(FFN*DD/4  + 255)/256, 256>>>(w2,    p_w2,   FFN*DD/4);

    ln_kernel<<<ROWS, 256>>>(x, g1, be1, p_ln);

    // grid: (M tiles, N tiles) — M fast-varying for weight-stream-once L2 reuse
    mm_tf32<EPI_TF32><<<dim3(ROWS/128, QKVN/256), 256, GEMM_SMEM>>>(
        p_ln, p_wqkv, p_qkv, nullptr, nullptr, ROWS, QKVN, DD);

    attn_mma<<<dim3(SS/QT, BB*HH), 256, ATTN_SMEM>>>(p_qkv, p_att);

    mm_tf32<EPI_RESID><<<dim3(ROWS/128, DD/256), 256, GEMM_SMEM>>>(
        p_att, p_wo, p_x2, nullptr, x, ROWS, DD, DD);

    ln_kernel<<<ROWS, 256>>>(p_x2, g2, be2, p_ln);

    mm_tf32<EPI_BIAS_GELU><<<dim3(ROWS/128, FFN/256), 256, GEMM_SMEM>>>(
        p_ln, p_w1, p_act, b1, nullptr, ROWS, FFN, DD);

    mm_tf32<EPI_BIAS_RESID><<<dim3(ROWS/128, DD/256), 256, GEMM_SMEM>>>(
        p_act, p_w2, out, b2, p_x2, ROWS, DD, FFN);
}

// round 7
// speedup vs baseline: 7.5888x; 1.5393x over previous
#include <cuda_runtime.h>
#include <cuda_fp16.h>
#include <cuda_bf16.h>
#include <math.h>
#include <stdint.h>

// Problem constants
#define BB 2
#define SS 2048
#define DD 2048
#define HH 16
#define HD 128
#define CHUNK 1024
#define ROWS (BB*SS)          // 4096
#define QKVN (3*DD)           // 6144
#define FFN  (4*DD)           // 8192

// ---------------- scratch ----------------------------------------------------
__device__ __half  g_ln16 [(size_t)ROWS*DD];      // LN out (A for qkv / w1)
__device__ float   g_qkv  [(size_t)ROWS*QKVN];    // fp32 (tf32-rounded) for attn
__device__ __half  g_att16[(size_t)ROWS*DD];      // attn out (A for w_o)
__device__ float   g_x2   [(size_t)ROWS*DD];      // residual stream (fp32)
__device__ __half  g_act16[(size_t)ROWS*FFN];     // gelu out (A for w2)
// fp16 k-pair-packed weights: [K/2][N] u32, low half = even k
__device__ uint32_t g_wqkvp[(size_t)(DD/2)*QKVN];
__device__ uint32_t g_wop [(size_t)(DD/2)*DD];
__device__ uint32_t g_w1p [(size_t)(DD/2)*FFN];
__device__ uint32_t g_w2p [(size_t)(FFN/2)*DD];

// ---------------- helpers ----------------------------------------------------
__device__ __forceinline__ float rtf32(float x) {
    uint32_t u;
    asm("cvt.rna.tf32.f32 %0, %1;" : "=r"(u) : "f"(x));
    return __uint_as_float(u);
}
__device__ __forceinline__ uint32_t s2u(const void* p) {
    uint32_t a;
    asm("{ .reg .u64 t; cvta.to.shared.u64 t, %1; cvt.u32.u64 %0, t; }"
        : "=r"(a) : "l"(p));
    return a;
}
__device__ __forceinline__ void cpasync16(uint32_t s, const void* g) {
    asm volatile("cp.async.cg.shared.global [%0], [%1], 16;" :: "r"(s), "l"(g));
}
__device__ __forceinline__ void mma_tf32(float* c, const uint32_t* a, const uint32_t* b) {
    asm volatile(
        "mma.sync.aligned.m16n8k8.row.col.f32.tf32.tf32.f32 "
        "{%0,%1,%2,%3}, {%4,%5,%6,%7}, {%8,%9}, {%0,%1,%2,%3};"
        : "+f"(c[0]), "+f"(c[1]), "+f"(c[2]), "+f"(c[3])
        : "r"(a[0]), "r"(a[1]), "r"(a[2]), "r"(a[3]), "r"(b[0]), "r"(b[1]));
}
__device__ __forceinline__ void mma_f16(float* c, const uint32_t* a,
                                        uint32_t b0, uint32_t b1) {
    asm volatile(
        "mma.sync.aligned.m16n8k16.row.col.f32.f16.f16.f32 "
        "{%0,%1,%2,%3}, {%4,%5,%6,%7}, {%8,%9}, {%0,%1,%2,%3};"
        : "+f"(c[0]), "+f"(c[1]), "+f"(c[2]), "+f"(c[3])
        : "r"(a[0]), "r"(a[1]), "r"(a[2]), "r"(a[3]), "r"(b0), "r"(b1));
}
__device__ __forceinline__ void ldsm_x4(uint32_t* r, uint32_t saddr) {
    asm volatile("ldmatrix.sync.aligned.m8n8.x4.shared.b16 {%0,%1,%2,%3}, [%4];"
                 : "=r"(r[0]), "=r"(r[1]), "=r"(r[2]), "=r"(r[3]) : "r"(saddr));
}

// ---------------- weight fp16 k-pair packing ---------------------------------
__global__ __launch_bounds__(256) void pack_w(const float* __restrict__ W,
                                              uint32_t* __restrict__ Wp, int N)
{
    const int n  = blockIdx.x * 256 + threadIdx.x;
    const int k2 = blockIdx.y;
    const float v0 = W[(size_t)(2 * k2)     * N + n];
    const float v1 = W[(size_t)(2 * k2 + 1) * N + n];
    __half2 h = __floats2half2_rn(v0, v1);
    Wp[(size_t)k2 * N + n] = *(uint32_t*)&h;
}

// ---------------- LayerNorm -> fp16 ------------------------------------------
__global__ __launch_bounds__(256) void ln_kernel(const float* __restrict__ x,
                                                 const float* __restrict__ g,
                                                 const float* __restrict__ be,
                                                 __half* __restrict__ y)
{
    const int row = blockIdx.x;
    const int tid = threadIdx.x;
    const float* xr = x + (size_t)row * DD;

    float4 v0 = *(const float4*)&xr[tid * 4];
    float4 v1 = *(const float4*)&xr[1024 + tid * 4];

    float s  = v0.x + v0.y + v0.z + v0.w + v1.x + v1.y + v1.z + v1.w;
    float ss = v0.x*v0.x + v0.y*v0.y + v0.z*v0.z + v0.w*v0.w
             + v1.x*v1.x + v1.y*v1.y + v1.z*v1.z + v1.w*v1.w;

    #pragma unroll
    for (int o = 16; o > 0; o >>= 1) {
        s  += __shfl_xor_sync(0xffffffffu, s,  o);
        ss += __shfl_xor_sync(0xffffffffu, ss, o);
    }
    __shared__ float rs[8], rss[8];
    __shared__ float mean_s, rstd_s;
    const int w = tid >> 5, ln = tid & 31;
    if (ln == 0) { rs[w] = s; rss[w] = ss; }
    __syncthreads();
    if (tid == 0) {
        float S = 0.f, SSQ = 0.f;
        #pragma unroll
        for (int i = 0; i < 8; i++) { S += rs[i]; SSQ += rss[i]; }
        float mean = S * (1.0f / DD);
        float var  = SSQ * (1.0f / DD) - mean * mean;
        mean_s = mean;
        rstd_s = rsqrtf(var + 1e-5f);
    }
    __syncthreads();
    const float mean = mean_s, rstd = rstd_s;

    float4 g0  = *(const float4*)&g [tid * 4];
    float4 g1  = *(const float4*)&g [1024 + tid * 4];
    float4 b0  = *(const float4*)&be[tid * 4];
    float4 b1  = *(const float4*)&be[1024 + tid * 4];

    __half2* yr = (__half2*)(y + (size_t)row * DD);
    yr[tid * 2]       = __floats2half2_rn((v0.x - mean) * rstd * g0.x + b0.x,
                                          (v0.y - mean) * rstd * g0.y + b0.y);
    yr[tid * 2 + 1]   = __floats2half2_rn((v0.z - mean) * rstd * g0.z + b0.z,
                                          (v0.w - mean) * rstd * g0.w + b0.w);
    yr[512 + tid * 2] = __floats2half2_rn((v1.x - mean) * rstd * g1.x + b1.x,
                                          (v1.y - mean) * rstd * g1.y + b1.y);
    yr[512 + tid*2+1] = __floats2half2_rn((v1.z - mean) * rstd * g1.z + b1.z,
                                          (v1.w - mean) * rstd * g1.w + b1.w);
}

// ---------------- fp16 mma GEMM: 128x256 CTA, grid (M-tiles, N-tiles) --------
#define EPI_RESID      1
#define EPI_BIAS_GELU  2
#define EPI_BIAS_RESID 3
#define EPI_TF32       4

#define AS_STRIDE 40                          // halves per A row
#define AS_BYTES  (128 * AS_STRIDE * 2)       // 10240
#define BS_STRIDE 264                         // u32 per B k-pair row
#define BS_BYTES  (16 * BS_STRIDE * 4)        // 16896
#define STAGE_BYTES (AS_BYTES + BS_BYTES)     // 27136
#define NSTAGE 3
#define GEMM_SMEM (NSTAGE * STAGE_BYTES)      // 81408

template<int EPI>
__global__ __launch_bounds__(256, 1)
void mm_f16(const __half* __restrict__ A, const uint32_t* __restrict__ Bp,
            void* __restrict__ Cv, const float* __restrict__ bias,
            const float* __restrict__ resid, int M, int N, int K)
{
    extern __shared__ char dyn[];
    constexpr bool OUTH = (EPI == EPI_BIAS_GELU);

    const int tid = threadIdx.x;
    const int wid = tid >> 5, lane = tid & 31;
    const int grp = lane >> 2, thr4 = lane & 3;
    const int wm = (wid >> 2) * 64;
    const int wn = (wid & 3) * 64;
    const int row0 = blockIdx.x * 128, col0 = blockIdx.y * 256;

    const int lrow = (lane & 7) + ((lane >> 3) & 1) * 8;   // ldsm row in 16
    const int lkof = (lane >> 4) * 8;                      // ldsm k offset

    const __half*   Ab = A  + (size_t)row0 * K;
    const uint32_t* Bb = Bp + col0;

    float acc[4][8][4];
    #pragma unroll
    for (int mi = 0; mi < 4; mi++)
        #pragma unroll
        for (int ni = 0; ni < 8; ni++)
            #pragma unroll
            for (int q = 0; q < 4; q++) acc[mi][ni][q] = 0.f;

    const int nk = K >> 5;                    // BK = 32 halves
    const uint32_t dynb = s2u(dyn);

    auto load_stage = [&](int kt, int buf) {
        const uint32_t as = dynb + buf * STAGE_BYTES;
        const uint32_t bs = as + AS_BYTES;
        const __half* ga = Ab + (size_t)kt * 32;
        #pragma unroll
        for (int i = 0; i < 2; i++) {         // A: 512 x 16B
            const int idx = tid + 256 * i;
            const int r = idx >> 2, c8 = idx & 3;
            cpasync16(as + (uint32_t)(r * AS_STRIDE + c8 * 8) * 2,
                      ga + (size_t)r * K + c8 * 8);
        }
        const uint32_t* gb = Bb + (size_t)(kt * 16) * N;
        #pragma unroll
        for (int i = 0; i < 4; i++) {         // B: 1024 x 16B
            const int idx = tid + 256 * i;
            const int kp = idx >> 6, n4 = idx & 63;
            cpasync16(bs + (uint32_t)(kp * BS_STRIDE + n4 * 4) * 4,
                      gb + (size_t)kp * N + n4 * 4);
        }
        asm volatile("cp.async.commit_group;");
    };

    load_stage(0, 0);
    load_stage(1, 1);

    for (int kt = 0; kt < nk; kt++) {
        if (kt == nk - 1) asm volatile("cp.async.wait_group 0;");
        else              asm volatile("cp.async.wait_group 1;");
        __syncthreads();

        if (kt + 2 < nk) load_stage(kt + 2, (kt + 2) % NSTAGE);

        const int cur = kt % NSTAGE;
        const uint32_t as_b = dynb + cur * STAGE_BYTES;
        const uint32_t* Bs = (const uint32_t*)(dyn + cur * STAGE_BYTES + AS_BYTES);

        #pragma unroll
        for (int s = 0; s < 2; s++) {         // two k16 sub-steps
            uint32_t a[4][4];
            #pragma unroll
            for (int mi = 0; mi < 4; mi++) {
                const uint32_t addr = as_b +
                    (uint32_t)(((wm + mi * 16 + lrow) * AS_STRIDE + s * 16 + lkof) * 2);
                ldsm_x4(a[mi], addr);
            }
            #pragma unroll
            for (int ni = 0; ni < 8; ni++) {
                const int n = wn + ni * 8 + grp;
                const uint32_t b0 = Bs[(s * 8 + thr4)     * BS_STRIDE + n];
                const uint32_t b1 = Bs[(s * 8 + thr4 + 4) * BS_STRIDE + n];
                #pragma unroll
                for (int mi = 0; mi < 4; mi++)
                    mma_f16(acc[mi][ni], a[mi], b0, b1);
            }
        }
        __syncthreads();
    }

    // ---- epilogue ----
    #pragma unroll
    for (int mi = 0; mi < 4; mi++) {
        #pragma unroll
        for (int half = 0; half < 2; half++) {
            const int r = row0 + wm + mi * 16 + grp + half * 8;
            #pragma unroll
            for (int ni = 0; ni < 8; ni++) {
                const int c = col0 + wn + ni * 8 + thr4 * 2;
                float v0 = acc[mi][ni][half * 2 + 0];
                float v1 = acc[mi][ni][half * 2 + 1];
                if (EPI == EPI_BIAS_GELU || EPI == EPI_BIAS_RESID) {
                    v0 += bias[c]; v1 += bias[c + 1];
                }
                if (EPI == EPI_RESID || EPI == EPI_BIAS_RESID) {
                    const float2 rr = *(const float2*)&resid[(size_t)r * N + c];
                    v0 += rr.x; v1 += rr.y;
                }
                if (EPI == EPI_BIAS_GELU) {
                    v0 = 0.5f * v0 * (1.0f + erff(v0 * 0.70710678118654752f));
                    v1 = 0.5f * v1 * (1.0f + erff(v1 * 0.70710678118654752f));
                }
                if (EPI == EPI_TF32) { v0 = rtf32(v0); v1 = rtf32(v1); }
                if (OUTH) {
                    ((__half2*)Cv)[((size_t)r * N + c) >> 1] =
                        __floats2half2_rn(v0, v1);
                } else {
                    float2 o; o.x = v0; o.y = v1;
                    *(float2*)&((float*)Cv)[(size_t)r * N + c] = o;
                }
            }
        }
    }
}

// ---------------- tensor-core flash attention (tf32, fp16 output) ------------
#define QT 128
#define KT 64
#define QS_STR 132
#define KS_STR 132
#define VS_STR 136
#define PS_STR 68
#define ATTN_SMEM ((QT*QS_STR + KT*KS_STR + KT*VS_STR + QT*PS_STR) * 4)

__global__ __launch_bounds__(256) void attn_mma(const float* __restrict__ qkv,
                                                __half* __restrict__ out)
{
    extern __shared__ float sm[];
    float* Qs = sm;
    float* Ks = Qs + QT * QS_STR;
    float* Vs = Ks + KT * KS_STR;
    float* Ps = Vs + KT * VS_STR;

    const int tid = threadIdx.x;
    const int wid = tid >> 5, lane = tid & 31;
    const int grp = lane >> 2, thr4 = lane & 3;
    const int qt = blockIdx.x, bh = blockIdx.y;
    const int b = bh >> 4, h = bh & 15;
    const int q0 = qt * QT;
    const float scale = 0.08838834764831845f;

    for (int i = tid; i < QT * 32; i += 256) {
        const int r = i >> 5, c4 = (i & 31) * 4;
        *(float4*)&Qs[r * QS_STR + c4] =
            *(const float4*)&qkv[(size_t)(b * SS + q0 + r) * QKVN + h * HD + c4];
    }

    const int r0 = wid * 16 + grp, r1 = r0 + 8;
    const int qmod0 = (q0 + r0) & (CHUNK - 1);
    const int qmod1 = (q0 + r1) & (CHUNK - 1);

    float O[16][4];
    #pragma unroll
    for (int nt = 0; nt < 16; nt++)
        #pragma unroll
        for (int q = 0; q < 4; q++) O[nt][q] = 0.f;
    float m0 = -1e30f, m1 = -1e30f, l0 = 0.f, l1 = 0.f;

    const int nkt = ((qt & 7) << 1) + 2;
    for (int kt = 0; kt < nkt; kt++) {
        const int kb = kt * KT;
        __syncthreads();
        for (int i = tid; i < KT * 32; i += 256) {
            const int r = i >> 5, c4 = (i & 31) * 4;
            const float* kp = &qkv[(size_t)(b * SS + kb + r) * QKVN + DD + h * HD + c4];
            *(float4*)&Ks[r * KS_STR + c4] = *(const float4*)kp;
            *(float4*)&Vs[r * VS_STR + c4] = *(const float4*)(kp + DD);
        }
        __syncthreads();

        float Sa[8][4];
        #pragma unroll
        for (int nt = 0; nt < 8; nt++)
            #pragma unroll
            for (int q = 0; q < 4; q++) Sa[nt][q] = 0.f;

        #pragma unroll
        for (int kk = 0; kk < HD; kk += 8) {
            uint32_t a[4];
            a[0] = __float_as_uint(Qs[r0 * QS_STR + kk + thr4]);
            a[1] = __float_as_uint(Qs[r1 * QS_STR + kk + thr4]);
            a[2] = __float_as_uint(Qs[r0 * QS_STR + kk + thr4 + 4]);
            a[3] = __float_as_uint(Qs[r1 * QS_STR + kk + thr4 + 4]);
            #pragma unroll
            for (int nt = 0; nt < 8; nt++) {
                uint32_t bfr[2];
                bfr[0] = __float_as_uint(Ks[(nt * 8 + grp) * KS_STR + kk + thr4]);
                bfr[1] = __float_as_uint(Ks[(nt * 8 + grp) * KS_STR + kk + thr4 + 4]);
                mma_tf32(Sa[nt], a, bfr);
            }
        }

        float mt0 = -1e30f, mt1 = -1e30f;
        #pragma unroll
        for (int nt = 0; nt < 8; nt++) {
            #pragma unroll
            for (int c = 0; c < 2; c++) {
                const int j = kb + nt * 8 + 2 * thr4 + c;
                Sa[nt][c]     = (j <= qmod0) ? Sa[nt][c]     * scale : -1e30f;
                Sa[nt][c + 2] = (j <= qmod1) ? Sa[nt][c + 2] * scale : -1e30f;
                mt0 = fmaxf(mt0, Sa[nt][c]);
                mt1 = fmaxf(mt1, Sa[nt][c + 2]);
            }
        }
        mt0 = fmaxf(mt0, __shfl_xor_sync(0xffffffffu, mt0, 1));
        mt0 = fmaxf(mt0, __shfl_xor_sync(0xffffffffu, mt0, 2));
        mt1 = fmaxf(mt1, __shfl_xor_sync(0xffffffffu, mt1, 1));
        mt1 = fmaxf(mt1, __shfl_xor_sync(0xffffffffu, mt1, 2));

        const float mn0 = fmaxf(m0, mt0), mn1 = fmaxf(m1, mt1);
        const float al0 = __expf(m0 - mn0), al1 = __expf(m1 - mn1);
        #pragma unroll
        for (int nt = 0; nt < 16; nt++) {
            O[nt][0] *= al0; O[nt][1] *= al0;
            O[nt][2] *= al1; O[nt][3] *= al1;
        }

        float s0 = 0.f, s1 = 0.f;
        #pragma unroll
        for (int nt = 0; nt < 8; nt++) {
            #pragma unroll
            for (int c = 0; c < 2; c++) {
                const int col = nt * 8 + 2 * thr4 + c;
                float p0 = rtf32(__expf(Sa[nt][c]     - mn0));
                float p1 = rtf32(__expf(Sa[nt][c + 2] - mn1));
                s0 += p0; s1 += p1;
                Ps[r0 * PS_STR + col] = p0;
                Ps[r1 * PS_STR + col] = p1;
            }
        }
        s0 += __shfl_xor_sync(0xffffffffu, s0, 1);
        s0 += __shfl_xor_sync(0xffffffffu, s0, 2);
        s1 += __shfl_xor_sync(0xffffffffu, s1, 1);
        s1 += __shfl_xor_sync(0xffffffffu, s1, 2);
        l0 = l0 * al0 + s0;  m0 = mn0;
        l1 = l1 * al1 + s1;  m1 = mn1;
        __syncwarp();

        #pragma unroll
        for (int kk = 0; kk < KT; kk += 8) {
            uint32_t a[4];
            a[0] = __float_as_uint(Ps[r0 * PS_STR + kk + thr4]);
            a[1] = __float_as_uint(Ps[r1 * PS_STR + kk + thr4]);
            a[2] = __float_as_uint(Ps[r0 * PS_STR + kk + thr4 + 4]);
            a[3] = __float_as_uint(Ps[r1 * PS_STR + kk + thr4 + 4]);
            #pragma unroll
            for (int nt = 0; nt < 16; nt++) {
                uint32_t bfr[2];
                bfr[0] = __float_as_uint(Vs[(kk + thr4) * VS_STR + nt * 8 + grp]);
                bfr[1] = __float_as_uint(Vs[(kk + thr4 + 4) * VS_STR + nt * 8 + grp]);
                mma_tf32(O[nt], a, bfr);
            }
        }
    }

    const float i0 = 1.0f / l0, i1 = 1.0f / l1;
    #pragma unroll
    for (int nt = 0; nt < 16; nt++) {
        const int c = h * HD + nt * 8 + 2 * thr4;
        *(__half2*)&out[(size_t)(b * SS + q0 + r0) * DD + c] =
            __floats2half2_rn(O[nt][0] * i0, O[nt][1] * i0);
        *(__half2*)&out[(size_t)(b * SS + q0 + r1) * DD + c] =
            __floats2half2_rn(O[nt][2] * i1, O[nt][3] * i1);
    }
}

// ---------------- launch ----------------------------------------------------
extern "C" void kernel_launch(void* const* d_in, const int* in_sizes, int n_in,
                              void* d_out, int out_size)
{
    const float* x     = (const float*)d_in[0];
    const float* w_qkv = (const float*)d_in[1];
    const float* w_o   = (const float*)d_in[2];
    const float* w1    = (const float*)d_in[3];
    const float* b1    = (const float*)d_in[4];
    const float* w2    = (const float*)d_in[5];
    const float* b2    = (const float*)d_in[6];
    const float* g1    = (const float*)d_in[7];
    const float* be1   = (const float*)d_in[8];
    const float* g2    = (const float*)d_in[9];
    const float* be2   = (const float*)d_in[10];
    float* out = (float*)d_out;

    __half *p_ln16, *p_att16, *p_act16;
    float *p_qkv, *p_x2;
    uint32_t *p_wqkvp, *p_wop, *p_w1p, *p_w2p;
    cudaGetSymbolAddress((void**)&p_ln16,  g_ln16);
    cudaGetSymbolAddress((void**)&p_qkv,   g_qkv);
    cudaGetSymbolAddress((void**)&p_att16, g_att16);
    cudaGetSymbolAddress((void**)&p_x2,    g_x2);
    cudaGetSymbolAddress((void**)&p_act16, g_act16);
    cudaGetSymbolAddress((void**)&p_wqkvp, g_wqkvp);
    cudaGetSymbolAddress((void**)&p_wop,   g_wop);
    cudaGetSymbolAddress((void**)&p_w1p,   g_w1p);
    cudaGetSymbolAddress((void**)&p_w2p,   g_w2p);

    cudaFuncSetAttribute(attn_mma,
                         cudaFuncAttributeMaxDynamicSharedMemorySize, ATTN_SMEM);
    cudaFuncSetAttribute(mm_f16<EPI_TF32>,
                         cudaFuncAttributeMaxDynamicSharedMemorySize, GEMM_SMEM);
    cudaFuncSetAttribute(mm_f16<EPI_RESID>,
                         cudaFuncAttributeMaxDynamicSharedMemorySize, GEMM_SMEM);
    cudaFuncSetAttribute(mm_f16<EPI_BIAS_GELU>,
                         cudaFuncAttributeMaxDynamicSharedMemorySize, GEMM_SMEM);
    cudaFuncSetAttribute(mm_f16<EPI_BIAS_RESID>,
                         cudaFuncAttributeMaxDynamicSharedMemorySize, GEMM_SMEM);

    // 0) pack weights to fp16 k-pair format (one-time)
    pack_w<<<dim3(QKVN/256, DD/2),  256>>>(w_qkv, p_wqkvp, QKVN);
    pack_w<<<dim3(DD/256,   DD/2),  256>>>(w_o,   p_wop,   DD);
    pack_w<<<dim3(FFN/256,  DD/2),  256>>>(w1,    p_w1p,   FFN);
    pack_w<<<dim3(DD/256,   FFN/2), 256>>>(w2,    p_w2p,   DD);

    // 1) LN1 -> fp16
    ln_kernel<<<ROWS, 256>>>(x, g1, be1, p_ln16);

    // 2) qkv = ln1 @ w_qkv  (fp32 out, tf32-rounded for attention)
    mm_f16<EPI_TF32><<<dim3(ROWS/128, QKVN/256), 256, GEMM_SMEM>>>(
        p_ln16, p_wqkvp, p_qkv, nullptr, nullptr, ROWS, QKVN, DD);

    // 3) attention -> fp16
    attn_mma<<<dim3(SS/QT, BB*HH), 256, ATTN_SMEM>>>(p_qkv, p_att16);

    // 4) x2 = attn @ w_o + x  (fp32)
    mm_f16<EPI_RESID><<<dim3(ROWS/128, DD/256), 256, GEMM_SMEM>>>(
        p_att16, p_wop, p_x2, nullptr, x, ROWS, DD, DD);

    // 5) LN2 -> fp16
    ln_kernel<<<ROWS, 256>>>(p_x2, g2, be2, p_ln16);

    // 6) act = gelu(ln2 @ w1 + b1) -> fp16
    mm_f16<EPI_BIAS_GELU><<<dim3(ROWS/128, FFN/256), 256, GEMM_SMEM>>>(
        p_ln16, p_w1p, p_act16, b1, nullptr, ROWS, FFN, DD);

    // 7) out = act @ w2 + b2 + x2  (fp32)
    mm_f16<EPI_BIAS_RESID><<<dim3(ROWS/128, DD/256), 256, GEMM_SMEM>>>(
        p_act16, p_w2p, out, b2, p_x2, ROWS, DD, FFN);
}

// round 8
// speedup vs baseline: 8.3295x; 1.0976x over previous
#include <cuda_runtime.h>
#include <cuda_fp16.h>
#include <math.h>
#include <stdint.h>

// Problem constants
#define BB 2
#define SS 2048
#define DD 2048
#define HH 16
#define HD 128
#define CHUNK 1024
#define ROWS (BB*SS)          // 4096
#define QKVN (3*DD)           // 6144
#define FFN  (4*DD)           // 8192

// ---------------- scratch ----------------------------------------------------
__device__ __half  g_ln16 [(size_t)ROWS*DD];
__device__ __half  g_qkv16[(size_t)ROWS*QKVN];
__device__ __half  g_att16[(size_t)ROWS*DD];
__device__ float   g_x2   [(size_t)ROWS*DD];
__device__ __half  g_act16[(size_t)ROWS*FFN];
__device__ uint32_t g_wqkvp[(size_t)(DD/2)*QKVN];
__device__ uint32_t g_wop [(size_t)(DD/2)*DD];
__device__ uint32_t g_w1p [(size_t)(DD/2)*FFN];
__device__ uint32_t g_w2p [(size_t)(FFN/2)*DD];

// ---------------- helpers ----------------------------------------------------
__device__ __forceinline__ uint32_t s2u(const void* p) {
    uint32_t a;
    asm("{ .reg .u64 t; cvta.to.shared.u64 t, %1; cvt.u32.u64 %0, t; }"
        : "=r"(a) : "l"(p));
    return a;
}
__device__ __forceinline__ void cpasync16(uint32_t s, const void* g) {
    asm volatile("cp.async.cg.shared.global [%0], [%1], 16;" :: "r"(s), "l"(g));
}
__device__ __forceinline__ void mma_f16(float* c, const uint32_t* a,
                                        uint32_t b0, uint32_t b1) {
    asm volatile(
        "mma.sync.aligned.m16n8k16.row.col.f32.f16.f16.f32 "
        "{%0,%1,%2,%3}, {%4,%5,%6,%7}, {%8,%9}, {%0,%1,%2,%3};"
        : "+f"(c[0]), "+f"(c[1]), "+f"(c[2]), "+f"(c[3])
        : "r"(a[0]), "r"(a[1]), "r"(a[2]), "r"(a[3]), "r"(b0), "r"(b1));
}
__device__ __forceinline__ void ldsm_x4(uint32_t* r, uint32_t saddr) {
    asm volatile("ldmatrix.sync.aligned.m8n8.x4.shared.b16 {%0,%1,%2,%3}, [%4];"
                 : "=r"(r[0]), "=r"(r[1]), "=r"(r[2]), "=r"(r[3]) : "r"(saddr));
}
__device__ __forceinline__ void ldsm_x4_t(uint32_t* r, uint32_t saddr) {
    asm volatile("ldmatrix.sync.aligned.m8n8.x4.trans.shared.b16 {%0,%1,%2,%3}, [%4];"
                 : "=r"(r[0]), "=r"(r[1]), "=r"(r[2]), "=r"(r[3]) : "r"(saddr));
}

// ---------------- weight fp16 k-pair packing ---------------------------------
__global__ __launch_bounds__(256) void pack_w(const float* __restrict__ W,
                                              uint32_t* __restrict__ Wp, int N)
{
    const int n  = blockIdx.x * 256 + threadIdx.x;
    const int k2 = blockIdx.y;
    const float v0 = W[(size_t)(2 * k2)     * N + n];
    const float v1 = W[(size_t)(2 * k2 + 1) * N + n];
    __half2 h = __floats2half2_rn(v0, v1);
    Wp[(size_t)k2 * N + n] = *(uint32_t*)&h;
}

// ---------------- LayerNorm -> fp16 ------------------------------------------
__global__ __launch_bounds__(256) void ln_kernel(const float* __restrict__ x,
                                                 const float* __restrict__ g,
                                                 const float* __restrict__ be,
                                                 __half* __restrict__ y)
{
    const int row = blockIdx.x;
    const int tid = threadIdx.x;
    const float* xr = x + (size_t)row * DD;

    float4 v0 = *(const float4*)&xr[tid * 4];
    float4 v1 = *(const float4*)&xr[1024 + tid * 4];

    float s  = v0.x + v0.y + v0.z + v0.w + v1.x + v1.y + v1.z + v1.w;
    float ss = v0.x*v0.x + v0.y*v0.y + v0.z*v0.z + v0.w*v0.w
             + v1.x*v1.x + v1.y*v1.y + v1.z*v1.z + v1.w*v1.w;

    #pragma unroll
    for (int o = 16; o > 0; o >>= 1) {
        s  += __shfl_xor_sync(0xffffffffu, s,  o);
        ss += __shfl_xor_sync(0xffffffffu, ss, o);
    }
    __shared__ float rs[8], rss[8];
    __shared__ float mean_s, rstd_s;
    const int w = tid >> 5, ln = tid & 31;
    if (ln == 0) { rs[w] = s; rss[w] = ss; }
    __syncthreads();
    if (tid == 0) {
        float S = 0.f, SSQ = 0.f;
        #pragma unroll
        for (int i = 0; i < 8; i++) { S += rs[i]; SSQ += rss[i]; }
        float mean = S * (1.0f / DD);
        float var  = SSQ * (1.0f / DD) - mean * mean;
        mean_s = mean;
        rstd_s = rsqrtf(var + 1e-5f);
    }
    __syncthreads();
    const float mean = mean_s, rstd = rstd_s;

    float4 g0  = *(const float4*)&g [tid * 4];
    float4 g1  = *(const float4*)&g [1024 + tid * 4];
    float4 b0  = *(const float4*)&be[tid * 4];
    float4 b1  = *(const float4*)&be[1024 + tid * 4];

    __half2* yr = (__half2*)(y + (size_t)row * DD);
    yr[tid * 2]       = __floats2half2_rn((v0.x - mean) * rstd * g0.x + b0.x,
                                          (v0.y - mean) * rstd * g0.y + b0.y);
    yr[tid * 2 + 1]   = __floats2half2_rn((v0.z - mean) * rstd * g0.z + b0.z,
                                          (v0.w - mean) * rstd * g0.w + b0.w);
    yr[512 + tid * 2] = __floats2half2_rn((v1.x - mean) * rstd * g1.x + b1.x,
                                          (v1.y - mean) * rstd * g1.y + b1.y);
    yr[512 + tid*2+1] = __floats2half2_rn((v1.z - mean) * rstd * g1.z + b1.z,
                                          (v1.w - mean) * rstd * g1.w + b1.w);
}

// ---------------- fp16 mma GEMM: 128x256 CTA, grid (M-tiles, N-tiles) --------
#define EPI_RESID      1
#define EPI_BIAS_GELU  2
#define EPI_BIAS_RESID 3
#define EPI_HALF       5

#define AS_STRIDE 40
#define AS_BYTES  (128 * AS_STRIDE * 2)
#define BS_STRIDE 264
#define BS_BYTES  (16 * BS_STRIDE * 4)
#define STAGE_BYTES (AS_BYTES + BS_BYTES)
#define NSTAGE 3
#define GEMM_SMEM (NSTAGE * STAGE_BYTES)

template<int EPI>
__global__ __launch_bounds__(256, 1)
void mm_f16(const __half* __restrict__ A, const uint32_t* __restrict__ Bp,
            void* __restrict__ Cv, const float* __restrict__ bias,
            const float* __restrict__ resid, int M, int N, int K)
{
    extern __shared__ char dyn[];
    constexpr bool OUTH = (EPI == EPI_BIAS_GELU || EPI == EPI_HALF);

    const int tid = threadIdx.x;
    const int wid = tid >> 5, lane = tid & 31;
    const int grp = lane >> 2, thr4 = lane & 3;
    const int wm = (wid >> 2) * 64;
    const int wn = (wid & 3) * 64;
    const int row0 = blockIdx.x * 128, col0 = blockIdx.y * 256;

    const int lrow = (lane & 7) + ((lane >> 3) & 1) * 8;
    const int lkof = (lane >> 4) * 8;

    const __half*   Ab = A  + (size_t)row0 * K;
    const uint32_t* Bb = Bp + col0;

    float acc[4][8][4];
    #pragma unroll
    for (int mi = 0; mi < 4; mi++)
        #pragma unroll
        for (int ni = 0; ni < 8; ni++)
            #pragma unroll
            for (int q = 0; q < 4; q++) acc[mi][ni][q] = 0.f;

    const int nk = K >> 5;
    const uint32_t dynb = s2u(dyn);

    auto load_stage = [&](int kt, int buf) {
        const uint32_t as = dynb + buf * STAGE_BYTES;
        const uint32_t bs = as + AS_BYTES;
        const __half* ga = Ab + (size_t)kt * 32;
        #pragma unroll
        for (int i = 0; i < 2; i++) {
            const int idx = tid + 256 * i;
            const int r = idx >> 2, c8 = idx & 3;
            cpasync16(as + (uint32_t)(r * AS_STRIDE + c8 * 8) * 2,
                      ga + (size_t)r * K + c8 * 8);
        }
        const uint32_t* gb = Bb + (size_t)(kt * 16) * N;
        #pragma unroll
        for (int i = 0; i < 4; i++) {
            const int idx = tid + 256 * i;
            const int kp = idx >> 6, n4 = idx & 63;
            cpasync16(bs + (uint32_t)(kp * BS_STRIDE + n4 * 4) * 4,
                      gb + (size_t)kp * N + n4 * 4);
        }
        asm volatile("cp.async.commit_group;");
    };

    load_stage(0, 0);
    load_stage(1, 1);

    for (int kt = 0; kt < nk; kt++) {
        if (kt == nk - 1) asm volatile("cp.async.wait_group 0;");
        else              asm volatile("cp.async.wait_group 1;");
        __syncthreads();

        if (kt + 2 < nk) load_stage(kt + 2, (kt + 2) % NSTAGE);

        const int cur = kt % NSTAGE;
        const uint32_t as_b = dynb + cur * STAGE_BYTES;
        const uint32_t* Bs = (const uint32_t*)(dyn + cur * STAGE_BYTES + AS_BYTES);

        #pragma unroll
        for (int s = 0; s < 2; s++) {
            uint32_t a[4][4];
            #pragma unroll
            for (int mi = 0; mi < 4; mi++) {
                const uint32_t addr = as_b +
                    (uint32_t)(((wm + mi * 16 + lrow) * AS_STRIDE + s * 16 + lkof) * 2);
                ldsm_x4(a[mi], addr);
            }
            #pragma unroll
            for (int ni = 0; ni < 8; ni++) {
                const int n = wn + ni * 8 + grp;
                const uint32_t b0 = Bs[(s * 8 + thr4)     * BS_STRIDE + n];
                const uint32_t b1 = Bs[(s * 8 + thr4 + 4) * BS_STRIDE + n];
                #pragma unroll
                for (int mi = 0; mi < 4; mi++)
                    mma_f16(acc[mi][ni], a[mi], b0, b1);
            }
        }
        __syncthreads();
    }

    // ---- epilogue ----
    #pragma unroll
    for (int mi = 0; mi < 4; mi++) {
        #pragma unroll
        for (int half = 0; half < 2; half++) {
            const int r = row0 + wm + mi * 16 + grp + half * 8;
            #pragma unroll
            for (int ni = 0; ni < 8; ni++) {
                const int c = col0 + wn + ni * 8 + thr4 * 2;
                float v0 = acc[mi][ni][half * 2 + 0];
                float v1 = acc[mi][ni][half * 2 + 1];
                if (EPI == EPI_BIAS_GELU || EPI == EPI_BIAS_RESID) {
                    v0 += bias[c]; v1 += bias[c + 1];
                }
                if (EPI == EPI_RESID || EPI == EPI_BIAS_RESID) {
                    const float2 rr = *(const float2*)&resid[(size_t)r * N + c];
                    v0 += rr.x; v1 += rr.y;
                }
                if (EPI == EPI_BIAS_GELU) {
                    v0 = 0.5f * v0 * (1.0f + erff(v0 * 0.70710678118654752f));
                    v1 = 0.5f * v1 * (1.0f + erff(v1 * 0.70710678118654752f));
                }
                if (OUTH) {
                    ((__half2*)Cv)[((size_t)r * N + c) >> 1] =
                        __floats2half2_rn(v0, v1);
                } else {
                    float2 o; o.x = v0; o.y = v1;
                    *(float2*)&((float*)Cv)[(size_t)r * N + c] = o;
                }
            }
        }
    }
}

// ---------------- fp16 flash attention (FA2-style register pipeline) ---------
#define QT 128
#define KT 64
#define QSH 136
#define KSH 136
#define VSH 136
#define ATTN_SMEM ((QT*QSH + KT*KSH + KT*VSH) * 2)   // 69632 bytes

__global__ __launch_bounds__(256) void attn_mma(const __half* __restrict__ qkv,
                                                __half* __restrict__ out)
{
    extern __shared__ __half smh[];
    __half* Qs = smh;
    __half* Ks = Qs + QT * QSH;
    __half* Vs = Ks + KT * KSH;

    const int tid = threadIdx.x;
    const int wid = tid >> 5, lane = tid & 31;
    const int grp = lane >> 2, thr4 = lane & 3;
    const int qt = blockIdx.x, bh = blockIdx.y;
    const int b = bh >> 4, h = bh & 15;
    const int q0 = qt * QT;
    const float scale = 0.08838834764831845f;

    const uint32_t qs_b = s2u(Qs), ks_b = s2u(Ks), vs_b = s2u(Vs);

    // load Q tile (128 rows x 128 halves)
    #pragma unroll
    for (int i = 0; i < 8; i++) {
        const int idx = tid + 256 * i;
        const int r = idx >> 4, c8 = (idx & 15) * 8;
        *(float4*)&Qs[r * QSH + c8] =
            *(const float4*)&qkv[(size_t)(b * SS + q0 + r) * QKVN + h * HD + c8];
    }

    const int r0 = wid * 16 + grp, r1 = r0 + 8;
    const int qmod0 = (q0 + r0) & (CHUNK - 1);
    const int qmod1 = (q0 + r1) & (CHUNK - 1);

    // ldsm lane addressing
    const int lrow = (lane & 7) + ((lane >> 3) & 1) * 8;   // Q A-frag row
    const int lkof = (lane >> 4) * 8;                      // Q A-frag k-offset
    const int kB_key = (lane >> 4) * 8 + (lane & 7);       // K B-frag: + nt2*16
    const int kB_kof = ((lane >> 3) & 1) * 8;              // K B-frag k-offset
    const int vB_key = ((lane >> 3) & 1) * 8 + (lane & 7); // V B-frag: + jj*16
    const int vB_dim = (lane >> 4) * 8;                    // V B-frag: + dt2*16

    float O[16][4];
    #pragma unroll
    for (int nt = 0; nt < 16; nt++)
        #pragma unroll
        for (int q = 0; q < 4; q++) O[nt][q] = 0.f;
    float m0 = -1e30f, m1 = -1e30f, l0 = 0.f, l1 = 0.f;

    const int nkt = ((qt & 7) << 1) + 2;
    for (int kt = 0; kt < nkt; kt++) {
        const int kb = kt * KT;
        __syncthreads();
        #pragma unroll
        for (int i = 0; i < 4; i++) {
            const int idx = tid + 256 * i;
            const int r = idx >> 4, c8 = (idx & 15) * 8;
            const __half* kp = &qkv[(size_t)(b * SS + kb + r) * QKVN + DD + h * HD + c8];
            *(float4*)&Ks[r * KSH + c8] = *(const float4*)kp;
            *(float4*)&Vs[r * VSH + c8] = *(const float4*)(kp + DD);
        }
        __syncthreads();

        // ---- S = Q K^T ----
        float Sa[8][4];
        #pragma unroll
        for (int nt = 0; nt < 8; nt++)
            #pragma unroll
            for (int q = 0; q < 4; q++) Sa[nt][q] = 0.f;

        #pragma unroll
        for (int j = 0; j < HD / 16; j++) {
            uint32_t aq[4];
            ldsm_x4(aq, qs_b +
                (uint32_t)(((wid * 16 + lrow) * QSH + j * 16 + lkof) * 2));
            #pragma unroll
            for (int nt2 = 0; nt2 < 4; nt2++) {
                uint32_t kb4[4];
                ldsm_x4(kb4, ks_b +
                    (uint32_t)(((nt2 * 16 + kB_key) * KSH + j * 16 + kB_kof) * 2));
                mma_f16(Sa[2 * nt2],     aq, kb4[0], kb4[1]);
                mma_f16(Sa[2 * nt2 + 1], aq, kb4[2], kb4[3]);
            }
        }

        // ---- mask + online softmax ----
        float mt0 = -1e30f, mt1 = -1e30f;
        #pragma unroll
        for (int nt = 0; nt < 8; nt++) {
            #pragma unroll
            for (int c = 0; c < 2; c++) {
                const int j = kb + nt * 8 + 2 * thr4 + c;
                Sa[nt][c]     = (j <= qmod0) ? Sa[nt][c]     * scale : -1e30f;
                Sa[nt][c + 2] = (j <= qmod1) ? Sa[nt][c + 2] * scale : -1e30f;
                mt0 = fmaxf(mt0, Sa[nt][c]);
                mt1 = fmaxf(mt1, Sa[nt][c + 2]);
            }
        }
        mt0 = fmaxf(mt0, __shfl_xor_sync(0xffffffffu, mt0, 1));
        mt0 = fmaxf(mt0, __shfl_xor_sync(0xffffffffu, mt0, 2));
        mt1 = fmaxf(mt1, __shfl_xor_sync(0xffffffffu, mt1, 1));
        mt1 = fmaxf(mt1, __shfl_xor_sync(0xffffffffu, mt1, 2));

        const float mn0 = fmaxf(m0, mt0), mn1 = fmaxf(m1, mt1);
        const float al0 = __expf(m0 - mn0), al1 = __expf(m1 - mn1);
        #pragma unroll
        for (int nt = 0; nt < 16; nt++) {
            O[nt][0] *= al0; O[nt][1] *= al0;
            O[nt][2] *= al1; O[nt][3] *= al1;
        }

        // ---- P in fp16 registers (C-frag -> A-frag direct) ----
        uint32_t pr0[8], pr1[8];
        float s0 = 0.f, s1 = 0.f;
        #pragma unroll
        for (int nt = 0; nt < 8; nt++) {
            __half2 h0 = __floats2half2_rn(__expf(Sa[nt][0] - mn0),
                                           __expf(Sa[nt][1] - mn0));
            __half2 h1 = __floats2half2_rn(__expf(Sa[nt][2] - mn1),
                                           __expf(Sa[nt][3] - mn1));
            pr0[nt] = *(uint32_t*)&h0;
            pr1[nt] = *(uint32_t*)&h1;
            const float2 f0 = __half22float2(h0);
            const float2 f1 = __half22float2(h1);
            s0 += f0.x + f0.y;
            s1 += f1.x + f1.y;
        }
        s0 += __shfl_xor_sync(0xffffffffu, s0, 1);
        s0 += __shfl_xor_sync(0xffffffffu, s0, 2);
        s1 += __shfl_xor_sync(0xffffffffu, s1, 1);
        s1 += __shfl_xor_sync(0xffffffffu, s1, 2);
        l0 = l0 * al0 + s0;  m0 = mn0;
        l1 = l1 * al1 + s1;  m1 = mn1;

        // ---- O += P @ V  (V^T via ldmatrix.trans) ----
        #pragma unroll
        for (int jj = 0; jj < KT / 16; jj++) {
            uint32_t ap[4];
            ap[0] = pr0[2 * jj];     ap[1] = pr1[2 * jj];
            ap[2] = pr0[2 * jj + 1]; ap[3] = pr1[2 * jj + 1];
            #pragma unroll
            for (int dt2 = 0; dt2 < 8; dt2++) {
                uint32_t vb4[4];
                ldsm_x4_t(vb4, vs_b +
                    (uint32_t)(((jj * 16 + vB_key) * VSH + dt2 * 16 + vB_dim) * 2));
                mma_f16(O[2 * dt2],     ap, vb4[0], vb4[1]);
                mma_f16(O[2 * dt2 + 1], ap, vb4[2], vb4[3]);
            }
        }
    }

    const float i0 = 1.0f / l0, i1 = 1.0f / l1;
    #pragma unroll
    for (int nt = 0; nt < 16; nt++) {
        const int c = h * HD + nt * 8 + 2 * thr4;
        *(__half2*)&out[(size_t)(b * SS + q0 + r0) * DD + c] =
            __floats2half2_rn(O[nt][0] * i0, O[nt][1] * i0);
        *(__half2*)&out[(size_t)(b * SS + q0 + r1) * DD + c] =
            __floats2half2_rn(O[nt][2] * i1, O[nt][3] * i1);
    }
}

// ---------------- launch ----------------------------------------------------
extern "C" void kernel_launch(void* const* d_in, const int* in_sizes, int n_in,
                              void* d_out, int out_size)
{
    const float* x     = (const float*)d_in[0];
    const float* w_qkv = (const float*)d_in[1];
    const float* w_o   = (const float*)d_in[2];
    const float* w1    = (const float*)d_in[3];
    const float* b1    = (const float*)d_in[4];
    const float* w2    = (const float*)d_in[5];
    const float* b2    = (const float*)d_in[6];
    const float* g1    = (const float*)d_in[7];
    const float* be1   = (const float*)d_in[8];
    const float* g2    = (const float*)d_in[9];
    const float* be2   = (const float*)d_in[10];
    float* out = (float*)d_out;

    __half *p_ln16, *p_qkv16, *p_att16, *p_act16;
    float *p_x2;
    uint32_t *p_wqkvp, *p_wop, *p_w1p, *p_w2p;
    cudaGetSymbolAddress((void**)&p_ln16,  g_ln16);
    cudaGetSymbolAddress((void**)&p_qkv16, g_qkv16);
    cudaGetSymbolAddress((void**)&p_att16, g_att16);
    cudaGetSymbolAddress((void**)&p_x2,    g_x2);
    cudaGetSymbolAddress((void**)&p_act16, g_act16);
    cudaGetSymbolAddress((void**)&p_wqkvp, g_wqkvp);
    cudaGetSymbolAddress((void**)&p_wop,   g_wop);
    cudaGetSymbolAddress((void**)&p_w1p,   g_w1p);
    cudaGetSymbolAddress((void**)&p_w2p,   g_w2p);

    cudaFuncSetAttribute(attn_mma,
                         cudaFuncAttributeMaxDynamicSharedMemorySize, ATTN_SMEM);
    cudaFuncSetAttribute(mm_f16<EPI_HALF>,
                         cudaFuncAttributeMaxDynamicSharedMemorySize, GEMM_SMEM);
    cudaFuncSetAttribute(mm_f16<EPI_RESID>,
                         cudaFuncAttributeMaxDynamicSharedMemorySize, GEMM_SMEM);
    cudaFuncSetAttribute(mm_f16<EPI_BIAS_GELU>,
                         cudaFuncAttributeMaxDynamicSharedMemorySize, GEMM_SMEM);
    cudaFuncSetAttribute(mm_f16<EPI_BIAS_RESID>,
                         cudaFuncAttributeMaxDynamicSharedMemorySize, GEMM_SMEM);

    // 0) pack weights to fp16 k-pair format
    pack_w<<<dim3(QKVN/256, DD/2),  256>>>(w_qkv, p_wqkvp, QKVN);
    pack_w<<<dim3(DD/256,   DD/2),  256>>>(w_o,   p_wop,   DD);
    pack_w<<<dim3(FFN/256,  DD/2),  256>>>(w1,    p_w1p,   FFN);
    pack_w<<<dim3(DD/256,   FFN/2), 256>>>(w2,    p_w2p,   DD);

    // 1) LN1 -> fp16
    ln_kernel<<<ROWS, 256>>>(x, g1, be1, p_ln16);

    // 2) qkv = ln1 @ w_qkv -> fp16
    mm_f16<EPI_HALF><<<dim3(ROWS/128, QKVN/256), 256, GEMM_SMEM>>>(
        p_ln16, p_wqkvp, p_qkv16, nullptr, nullptr, ROWS, QKVN, DD);

    // 3) attention (fp16 tensor cores) -> fp16
    attn_mma<<<dim3(SS/QT, BB*HH), 256, ATTN_SMEM>>>(p_qkv16, p_att16);

    // 4) x2 = attn @ w_o + x  (fp32)
    mm_f16<EPI_RESID><<<dim3(ROWS/128, DD/256), 256, GEMM_SMEM>>>(
        p_att16, p_wop, p_x2, nullptr, x, ROWS, DD, DD);

    // 5) LN2 -> fp16
    ln_kernel<<<ROWS, 256>>>(p_x2, g2, be2, p_ln16);

    // 6) act = gelu(ln2 @ w1 + b1) -> fp16
    mm_f16<EPI_BIAS_GELU><<<dim3(ROWS/128, FFN/256), 256, GEMM_SMEM>>>(
        p_ln16, p_w1p, p_act16, b1, nullptr, ROWS, FFN, DD);

    // 7) out = act @ w2 + b2 + x2  (fp32)
    mm_f16<EPI_BIAS_RESID><<<dim3(ROWS/128, DD/256), 256, GEMM_SMEM>>>(
        p_act16, p_w2p, out, b2, p_x2, ROWS, DD, FFN);
}

// round 9
// speedup vs baseline: 8.5290x; 1.0240x over previous
#include <cuda_runtime.h>
#include <cuda_fp16.h>
#include <math.h>
#include <stdint.h>

// Problem constants
#define BB 2
#define SS 2048
#define DD 2048
#define HH 16
#define HD 128
#define CHUNK 1024
#define ROWS (BB*SS)          // 4096
#define QKVN (3*DD)           // 6144
#define FFN  (4*DD)           // 8192

// ---------------- scratch ----------------------------------------------------
__device__ __half  g_ln16 [(size_t)ROWS*DD];
__device__ __half  g_qkv16[(size_t)ROWS*QKVN];
__device__ __half  g_att16[(size_t)ROWS*DD];
__device__ float   g_x2   [(size_t)ROWS*DD];
__device__ __half  g_act16[(size_t)ROWS*FFN];
__device__ uint32_t g_wqkvp[(size_t)(DD/2)*QKVN];
__device__ uint32_t g_wop [(size_t)(DD/2)*DD];
__device__ uint32_t g_w1p [(size_t)(DD/2)*FFN];
__device__ uint32_t g_w2p [(size_t)(FFN/2)*DD];

// ---------------- helpers ----------------------------------------------------
__device__ __forceinline__ uint32_t s2u(const void* p) {
    uint32_t a;
    asm("{ .reg .u64 t; cvta.to.shared.u64 t, %1; cvt.u32.u64 %0, t; }"
        : "=r"(a) : "l"(p));
    return a;
}
__device__ __forceinline__ void cpasync16(uint32_t s, const void* g) {
    asm volatile("cp.async.cg.shared.global [%0], [%1], 16;" :: "r"(s), "l"(g));
}
__device__ __forceinline__ void mma_f16(float* c, const uint32_t* a,
                                        uint32_t b0, uint32_t b1) {
    asm volatile(
        "mma.sync.aligned.m16n8k16.row.col.f32.f16.f16.f32 "
        "{%0,%1,%2,%3}, {%4,%5,%6,%7}, {%8,%9}, {%0,%1,%2,%3};"
        : "+f"(c[0]), "+f"(c[1]), "+f"(c[2]), "+f"(c[3])
        : "r"(a[0]), "r"(a[1]), "r"(a[2]), "r"(a[3]), "r"(b0), "r"(b1));
}
__device__ __forceinline__ void ldsm_x4(uint32_t* r, uint32_t saddr) {
    asm volatile("ldmatrix.sync.aligned.m8n8.x4.shared.b16 {%0,%1,%2,%3}, [%4];"
                 : "=r"(r[0]), "=r"(r[1]), "=r"(r[2]), "=r"(r[3]) : "r"(saddr));
}
__device__ __forceinline__ void ldsm_x4_t(uint32_t* r, uint32_t saddr) {
    asm volatile("ldmatrix.sync.aligned.m8n8.x4.trans.shared.b16 {%0,%1,%2,%3}, [%4];"
                 : "=r"(r[0]), "=r"(r[1]), "=r"(r[2]), "=r"(r[3]) : "r"(saddr));
}

// ---------------- weight fp16 k-pair packing ---------------------------------
__global__ __launch_bounds__(256) void pack_w(const float* __restrict__ W,
                                              uint32_t* __restrict__ Wp, int N)
{
    const int n  = blockIdx.x * 256 + threadIdx.x;
    const int k2 = blockIdx.y;
    const float v0 = W[(size_t)(2 * k2)     * N + n];
    const float v1 = W[(size_t)(2 * k2 + 1) * N + n];
    __half2 h = __floats2half2_rn(v0, v1);
    Wp[(size_t)k2 * N + n] = *(uint32_t*)&h;
}

// ---------------- LayerNorm -> fp16 ------------------------------------------
__global__ __launch_bounds__(256) void ln_kernel(const float* __restrict__ x,
                                                 const float* __restrict__ g,
                                                 const float* __restrict__ be,
                                                 __half* __restrict__ y)
{
    const int row = blockIdx.x;
    const int tid = threadIdx.x;
    const float* xr = x + (size_t)row * DD;

    float4 v0 = *(const float4*)&xr[tid * 4];
    float4 v1 = *(const float4*)&xr[1024 + tid * 4];

    float s  = v0.x + v0.y + v0.z + v0.w + v1.x + v1.y + v1.z + v1.w;
    float ss = v0.x*v0.x + v0.y*v0.y + v0.z*v0.z + v0.w*v0.w
             + v1.x*v1.x + v1.y*v1.y + v1.z*v1.z + v1.w*v1.w;

    #pragma unroll
    for (int o = 16; o > 0; o >>= 1) {
        s  += __shfl_xor_sync(0xffffffffu, s,  o);
        ss += __shfl_xor_sync(0xffffffffu, ss, o);
    }
    __shared__ float rs[8], rss[8];
    __shared__ float mean_s, rstd_s;
    const int w = tid >> 5, ln = tid & 31;
    if (ln == 0) { rs[w] = s; rss[w] = ss; }
    __syncthreads();
    if (tid == 0) {
        float S = 0.f, SSQ = 0.f;
        #pragma unroll
        for (int i = 0; i < 8; i++) { S += rs[i]; SSQ += rss[i]; }
        float mean = S * (1.0f / DD);
        float var  = SSQ * (1.0f / DD) - mean * mean;
        mean_s = mean;
        rstd_s = rsqrtf(var + 1e-5f);
    }
    __syncthreads();
    const float mean = mean_s, rstd = rstd_s;

    float4 g0  = *(const float4*)&g [tid * 4];
    float4 g1  = *(const float4*)&g [1024 + tid * 4];
    float4 b0  = *(const float4*)&be[tid * 4];
    float4 b1  = *(const float4*)&be[1024 + tid * 4];

    __half2* yr = (__half2*)(y + (size_t)row * DD);
    yr[tid * 2]       = __floats2half2_rn((v0.x - mean) * rstd * g0.x + b0.x,
                                          (v0.y - mean) * rstd * g0.y + b0.y);
    yr[tid * 2 + 1]   = __floats2half2_rn((v0.z - mean) * rstd * g0.z + b0.z,
                                          (v0.w - mean) * rstd * g0.w + b0.w);
    yr[512 + tid * 2] = __floats2half2_rn((v1.x - mean) * rstd * g1.x + b1.x,
                                          (v1.y - mean) * rstd * g1.y + b1.y);
    yr[512 + tid*2+1] = __floats2half2_rn((v1.z - mean) * rstd * g1.z + b1.z,
                                          (v1.w - mean) * rstd * g1.w + b1.w);
}

// ---------------- fp16 mma GEMM: 128x256 CTA, grid (M-tiles, N-tiles) --------
#define EPI_RESID      1
#define EPI_BIAS_GELU  2
#define EPI_BIAS_RESID 3
#define EPI_HALF       5

#define AS_STRIDE 40
#define AS_BYTES  (128 * AS_STRIDE * 2)
#define BS_STRIDE 264
#define BS_BYTES  (16 * BS_STRIDE * 4)
#define STAGE_BYTES (AS_BYTES + BS_BYTES)
#define NSTAGE 3
#define GEMM_SMEM (NSTAGE * STAGE_BYTES)

template<int EPI>
__global__ __launch_bounds__(256, 1)
void mm_f16(const __half* __restrict__ A, const uint32_t* __restrict__ Bp,
            void* __restrict__ Cv, const float* __restrict__ bias,
            const float* __restrict__ resid, int M, int N, int K)
{
    extern __shared__ char dyn[];
    constexpr bool OUTH = (EPI == EPI_BIAS_GELU || EPI == EPI_HALF);

    const int tid = threadIdx.x;
    const int wid = tid >> 5, lane = tid & 31;
    const int grp = lane >> 2, thr4 = lane & 3;
    const int wm = (wid >> 2) * 64;
    const int wn = (wid & 3) * 64;
    const int row0 = blockIdx.x * 128, col0 = blockIdx.y * 256;

    const int lrow = (lane & 7) + ((lane >> 3) & 1) * 8;
    const int lkof = (lane >> 4) * 8;

    const __half*   Ab = A  + (size_t)row0 * K;
    const uint32_t* Bb = Bp + col0;

    float acc[4][8][4];
    #pragma unroll
    for (int mi = 0; mi < 4; mi++)
        #pragma unroll
        for (int ni = 0; ni < 8; ni++)
            #pragma unroll
            for (int q = 0; q < 4; q++) acc[mi][ni][q] = 0.f;

    const int nk = K >> 5;
    const uint32_t dynb = s2u(dyn);

    auto load_stage = [&](int kt, int buf) {
        const uint32_t as = dynb + buf * STAGE_BYTES;
        const uint32_t bs = as + AS_BYTES;
        const __half* ga = Ab + (size_t)kt * 32;
        #pragma unroll
        for (int i = 0; i < 2; i++) {
            const int idx = tid + 256 * i;
            const int r = idx >> 2, c8 = idx & 3;
            cpasync16(as + (uint32_t)(r * AS_STRIDE + c8 * 8) * 2,
                      ga + (size_t)r * K + c8 * 8);
        }
        const uint32_t* gb = Bb + (size_t)(kt * 16) * N;
        #pragma unroll
        for (int i = 0; i < 4; i++) {
            const int idx = tid + 256 * i;
            const int kp = idx >> 6, n4 = idx & 63;
            cpasync16(bs + (uint32_t)(kp * BS_STRIDE + n4 * 4) * 4,
                      gb + (size_t)kp * N + n4 * 4);
        }
        asm volatile("cp.async.commit_group;");
    };

    load_stage(0, 0);
    load_stage(1, 1);

    for (int kt = 0; kt < nk; kt++) {
        if (kt == nk - 1) asm volatile("cp.async.wait_group 0;");
        else              asm volatile("cp.async.wait_group 1;");
        __syncthreads();   // single barrier per iteration (protects stage reuse)

        if (kt + 2 < nk) load_stage(kt + 2, (kt + 2) % NSTAGE);

        const int cur = kt % NSTAGE;
        const uint32_t as_b = dynb + cur * STAGE_BYTES;
        const uint32_t* Bs = (const uint32_t*)(dyn + cur * STAGE_BYTES + AS_BYTES);

        #pragma unroll
        for (int s = 0; s < 2; s++) {
            uint32_t a[4][4];
            #pragma unroll
            for (int mi = 0; mi < 4; mi++) {
                const uint32_t addr = as_b +
                    (uint32_t)(((wm + mi * 16 + lrow) * AS_STRIDE + s * 16 + lkof) * 2);
                ldsm_x4(a[mi], addr);
            }
            #pragma unroll
            for (int ni = 0; ni < 8; ni++) {
                const int n = wn + ni * 8 + grp;
                const uint32_t b0 = Bs[(s * 8 + thr4)     * BS_STRIDE + n];
                const uint32_t b1 = Bs[(s * 8 + thr4 + 4) * BS_STRIDE + n];
                #pragma unroll
                for (int mi = 0; mi < 4; mi++)
                    mma_f16(acc[mi][ni], a[mi], b0, b1);
            }
        }
        // no trailing barrier: next iteration's top barrier protects reuse
    }

    // ---- epilogue ----
    #pragma unroll
    for (int mi = 0; mi < 4; mi++) {
        #pragma unroll
        for (int half = 0; half < 2; half++) {
            const int r = row0 + wm + mi * 16 + grp + half * 8;
            #pragma unroll
            for (int ni = 0; ni < 8; ni++) {
                const int c = col0 + wn + ni * 8 + thr4 * 2;
                float v0 = acc[mi][ni][half * 2 + 0];
                float v1 = acc[mi][ni][half * 2 + 1];
                if (EPI == EPI_BIAS_GELU || EPI == EPI_BIAS_RESID) {
                    v0 += bias[c]; v1 += bias[c + 1];
                }
                if (EPI == EPI_RESID || EPI == EPI_BIAS_RESID) {
                    const float2 rr = *(const float2*)&resid[(size_t)r * N + c];
                    v0 += rr.x; v1 += rr.y;
                }
                if (EPI == EPI_BIAS_GELU) {
                    v0 = 0.5f * v0 * (1.0f + erff(v0 * 0.70710678118654752f));
                    v1 = 0.5f * v1 * (1.0f + erff(v1 * 0.70710678118654752f));
                }
                if (OUTH) {
                    ((__half2*)Cv)[((size_t)r * N + c) >> 1] =
                        __floats2half2_rn(v0, v1);
                } else {
                    float2 o; o.x = v0; o.y = v1;
                    *(float2*)&((float*)Cv)[(size_t)r * N + c] = o;
                }
            }
        }
    }
}

// ---------------- fp16 flash attention (double-buffered KV, Q-frag hoist) ----
#define QT 128
#define KT 64
#define QSH 136
#define KSH 136
#define VSH 136
#define KVBUF (KT * KSH * 2)                       // bytes per K (or V) buffer
#define ATTN_SMEM ((QT*QSH + 4*KT*KSH) * 2)        // 104448 bytes

__global__ __launch_bounds__(256) void attn_mma(const __half* __restrict__ qkv,
                                                __half* __restrict__ out)
{
    extern __shared__ __half smh[];
    __half* Qs  = smh;
    __half* Ks0 = Qs + QT * QSH;
    __half* Vs0 = Ks0 + 2 * KT * KSH;

    const int tid = threadIdx.x;
    const int wid = tid >> 5, lane = tid & 31;
    const int grp = lane >> 2, thr4 = lane & 3;
    const int qt = blockIdx.x, bh = blockIdx.y;
    const int b = bh >> 4, h = bh & 15;
    const int q0 = qt * QT;
    const float scale = 0.08838834764831845f;

    const uint32_t qs_b = s2u(Qs), ks0_b = s2u(Ks0), vs0_b = s2u(Vs0);

    // load Q tile (direct stores)
    #pragma unroll
    for (int i = 0; i < 8; i++) {
        const int idx = tid + 256 * i;
        const int r = idx >> 4, c8 = (idx & 15) * 8;
        *(float4*)&Qs[r * QSH + c8] =
            *(const float4*)&qkv[(size_t)(b * SS + q0 + r) * QKVN + h * HD + c8];
    }

    // cp.async K/V tile loader
    auto load_kv = [&](int kt, int buf) {
        const int kb = kt * KT;
        const uint32_t kd = ks0_b + (uint32_t)buf * KVBUF;
        const uint32_t vd = vs0_b + (uint32_t)buf * KVBUF;
        #pragma unroll
        for (int i = 0; i < 4; i++) {
            const int idx = tid + 256 * i;
            const int r = idx >> 4, c8 = (idx & 15) * 8;
            const __half* src =
                &qkv[(size_t)(b * SS + kb + r) * QKVN + DD + h * HD + c8];
            cpasync16(kd + (uint32_t)(r * KSH + c8) * 2, src);
            cpasync16(vd + (uint32_t)(r * VSH + c8) * 2, src + DD);
        }
        asm volatile("cp.async.commit_group;");
    };

    const int nkt = ((qt & 7) << 1) + 2;
    load_kv(0, 0);

    const int r0 = wid * 16 + grp, r1 = r0 + 8;
    const int qmod0 = (q0 + r0) & (CHUNK - 1);
    const int qmod1 = (q0 + r1) & (CHUNK - 1);

    // ldsm lane addressing
    const int lrow = (lane & 7) + ((lane >> 3) & 1) * 8;
    const int lkof = (lane >> 4) * 8;
    const int kB_key = (lane >> 4) * 8 + (lane & 7);
    const int kB_kof = ((lane >> 3) & 1) * 8;
    const int vB_key = ((lane >> 3) & 1) * 8 + (lane & 7);
    const int vB_dim = (lane >> 4) * 8;

    // hoist Q fragments (loop-invariant) — barrier covers Q stores
    __syncthreads();
    uint32_t qa[8][4];
    #pragma unroll
    for (int j = 0; j < HD / 16; j++)
        ldsm_x4(qa[j], qs_b +
            (uint32_t)(((wid * 16 + lrow) * QSH + j * 16 + lkof) * 2));

    float O[16][4];
    #pragma unroll
    for (int nt = 0; nt < 16; nt++)
        #pragma unroll
        for (int q = 0; q < 4; q++) O[nt][q] = 0.f;
    float m0 = -1e30f, m1 = -1e30f, l0 = 0.f, l1 = 0.f;

    for (int kt = 0; kt < nkt; kt++) {
        const int kb = kt * KT;
        const int buf = kt & 1;
        asm volatile("cp.async.wait_group 0;");
        __syncthreads();
        if (kt + 1 < nkt) load_kv(kt + 1, buf ^ 1);   // overlap with compute

        const uint32_t ks_b = ks0_b + (uint32_t)buf * KVBUF;
        const uint32_t vs_b = vs0_b + (uint32_t)buf * KVBUF;

        // ---- S = Q K^T ----
        float Sa[8][4];
        #pragma unroll
        for (int nt = 0; nt < 8; nt++)
            #pragma unroll
            for (int q = 0; q < 4; q++) Sa[nt][q] = 0.f;

        #pragma unroll
        for (int j = 0; j < HD / 16; j++) {
            #pragma unroll
            for (int nt2 = 0; nt2 < 4; nt2++) {
                uint32_t kb4[4];
                ldsm_x4(kb4, ks_b +
                    (uint32_t)(((nt2 * 16 + kB_key) * KSH + j * 16 + kB_kof) * 2));
                mma_f16(Sa[2 * nt2],     qa[j], kb4[0], kb4[1]);
                mma_f16(Sa[2 * nt2 + 1], qa[j], kb4[2], kb4[3]);
            }
        }

        // ---- mask + online softmax ----
        float mt0 = -1e30f, mt1 = -1e30f;
        #pragma unroll
        for (int nt = 0; nt < 8; nt++) {
            #pragma unroll
            for (int c = 0; c < 2; c++) {
                const int j = kb + nt * 8 + 2 * thr4 + c;
                Sa[nt][c]     = (j <= qmod0) ? Sa[nt][c]     * scale : -1e30f;
                Sa[nt][c + 2] = (j <= qmod1) ? Sa[nt][c + 2] * scale : -1e30f;
                mt0 = fmaxf(mt0, Sa[nt][c]);
                mt1 = fmaxf(mt1, Sa[nt][c + 2]);
            }
        }
        mt0 = fmaxf(mt0, __shfl_xor_sync(0xffffffffu, mt0, 1));
        mt0 = fmaxf(mt0, __shfl_xor_sync(0xffffffffu, mt0, 2));
        mt1 = fmaxf(mt1, __shfl_xor_sync(0xffffffffu, mt1, 1));
        mt1 = fmaxf(mt1, __shfl_xor_sync(0xffffffffu, mt1, 2));

        const float mn0 = fmaxf(m0, mt0), mn1 = fmaxf(m1, mt1);
        const float al0 = __expf(m0 - mn0), al1 = __expf(m1 - mn1);
        #pragma unroll
        for (int nt = 0; nt < 16; nt++) {
            O[nt][0] *= al0; O[nt][1] *= al0;
            O[nt][2] *= al1; O[nt][3] *= al1;
        }

        // ---- P in fp16 registers ----
        uint32_t pr0[8], pr1[8];
        float s0 = 0.f, s1 = 0.f;
        #pragma unroll
        for (int nt = 0; nt < 8; nt++) {
            __half2 h0 = __floats2half2_rn(__expf(Sa[nt][0] - mn0),
                                           __expf(Sa[nt][1] - mn0));
            __half2 h1 = __floats2half2_rn(__expf(Sa[nt][2] - mn1),
                                           __expf(Sa[nt][3] - mn1));
            pr0[nt] = *(uint32_t*)&h0;
            pr1[nt] = *(uint32_t*)&h1;
            const float2 f0 = __half22float2(h0);
            const float2 f1 = __half22float2(h1);
            s0 += f0.x + f0.y;
            s1 += f1.x + f1.y;
        }
        s0 += __shfl_xor_sync(0xffffffffu, s0, 1);
        s0 += __shfl_xor_sync(0xffffffffu, s0, 2);
        s1 += __shfl_xor_sync(0xffffffffu, s1, 1);
        s1 += __shfl_xor_sync(0xffffffffu, s1, 2);
        l0 = l0 * al0 + s0;  m0 = mn0;
        l1 = l1 * al1 + s1;  m1 = mn1;

        // ---- O += P @ V ----
        #pragma unroll
        for (int jj = 0; jj < KT / 16; jj++) {
            uint32_t ap[4];
            ap[0] = pr0[2 * jj];     ap[1] = pr1[2 * jj];
            ap[2] = pr0[2 * jj + 1]; ap[3] = pr1[2 * jj + 1];
            #pragma unroll
            for (int dt2 = 0; dt2 < 8; dt2++) {
                uint32_t vb4[4];
                ldsm_x4_t(vb4, vs_b +
                    (uint32_t)(((jj * 16 + vB_key) * VSH + dt2 * 16 + vB_dim) * 2));
                mma_f16(O[2 * dt2],     ap, vb4[0], vb4[1]);
                mma_f16(O[2 * dt2 + 1], ap, vb4[2], vb4[3]);
            }
        }
    }

    const float i0 = 1.0f / l0, i1 = 1.0f / l1;
    #pragma unroll
    for (int nt = 0; nt < 16; nt++) {
        const int c = h * HD + nt * 8 + 2 * thr4;
        *(__half2*)&out[(size_t)(b * SS + q0 + r0) * DD + c] =
            __floats2half2_rn(O[nt][0] * i0, O[nt][1] * i0);
        *(__half2*)&out[(size_t)(b * SS + q0 + r1) * DD + c] =
            __floats2half2_rn(O[nt][2] * i1, O[nt][3] * i1);
    }
}

// ---------------- launch ----------------------------------------------------
extern "C" void kernel_launch(void* const* d_in, const int* in_sizes, int n_in,
                              void* d_out, int out_size)
{
    const float* x     = (const float*)d_in[0];
    const float* w_qkv = (const float*)d_in[1];
    const float* w_o   = (const float*)d_in[2];
    const float* w1    = (const float*)d_in[3];
    const float* b1    = (const float*)d_in[4];
    const float* w2    = (const float*)d_in[5];
    const float* b2    = (const float*)d_in[6];
    const float* g1    = (const float*)d_in[7];
    const float* be1   = (const float*)d_in[8];
    const float* g2    = (const float*)d_in[9];
    const float* be2   = (const float*)d_in[10];
    float* out = (float*)d_out;

    __half *p_ln16, *p_qkv16, *p_att16, *p_act16;
    float *p_x2;
    uint32_t *p_wqkvp, *p_wop, *p_w1p, *p_w2p;
    cudaGetSymbolAddress((void**)&p_ln16,  g_ln16);
    cudaGetSymbolAddress((void**)&p_qkv16, g_qkv16);
    cudaGetSymbolAddress((void**)&p_att16, g_att16);
    cudaGetSymbolAddress((void**)&p_x2,    g_x2);
    cudaGetSymbolAddress((void**)&p_act16, g_act16);
    cudaGetSymbolAddress((void**)&p_wqkvp, g_wqkvp);
    cudaGetSymbolAddress((void**)&p_wop,   g_wop);
    cudaGetSymbolAddress((void**)&p_w1p,   g_w1p);
    cudaGetSymbolAddress((void**)&p_w2p,   g_w2p);

    cudaFuncSetAttribute(attn_mma,
                         cudaFuncAttributeMaxDynamicSharedMemorySize, ATTN_SMEM);
    cudaFuncSetAttribute(mm_f16<EPI_HALF>,
                         cudaFuncAttributeMaxDynamicSharedMemorySize, GEMM_SMEM);
    cudaFuncSetAttribute(mm_f16<EPI_RESID>,
                         cudaFuncAttributeMaxDynamicSharedMemorySize, GEMM_SMEM);
    cudaFuncSetAttribute(mm_f16<EPI_BIAS_GELU>,
                         cudaFuncAttributeMaxDynamicSharedMemorySize, GEMM_SMEM);
    cudaFuncSetAttribute(mm_f16<EPI_BIAS_RESID>,
                         cudaFuncAttributeMaxDynamicSharedMemorySize, GEMM_SMEM);

    // 0) pack weights to fp16 k-pair format
    pack_w<<<dim3(QKVN/256, DD/2),  256>>>(w_qkv, p_wqkvp, QKVN);
    pack_w<<<dim3(DD/256,   DD/2),  256>>>(w_o,   p_wop,   DD);
    pack_w<<<dim3(FFN/256,  DD/2),  256>>>(w1,    p_w1p,   FFN);
    pack_w<<<dim3(DD/256,   FFN/2), 256>>>(w2,    p_w2p,   DD);

    // 1) LN1 -> fp16
    ln_kernel<<<ROWS, 256>>>(x, g1, be1, p_ln16);

    // 2) qkv = ln1 @ w_qkv -> fp16
    mm_f16<EPI_HALF><<<dim3(ROWS/128, QKVN/256), 256, GEMM_SMEM>>>(
        p_ln16, p_wqkvp, p_qkv16, nullptr, nullptr, ROWS, QKVN, DD);

    // 3) attention (fp16 tensor cores) -> fp16
    attn_mma<<<dim3(SS/QT, BB*HH), 256, ATTN_SMEM>>>(p_qkv16, p_att16);

    // 4) x2 = attn @ w_o + x  (fp32)
    mm_f16<EPI_RESID><<<dim3(ROWS/128, DD/256), 256, GEMM_SMEM>>>(
        p_att16, p_wop, p_x2, nullptr, x, ROWS, DD, DD);

    // 5) LN2 -> fp16
    ln_kernel<<<ROWS, 256>>>(p_x2, g2, be2, p_ln16);

    // 6) act = gelu(ln2 @ w1 + b1) -> fp16
    mm_f16<EPI_BIAS_GELU><<<dim3(ROWS/128, FFN/256), 256, GEMM_SMEM>>>(
        p_ln16, p_w1p, p_act16, b1, nullptr, ROWS, FFN, DD);

    // 7) out = act @ w2 + b2 + x2  (fp32)
    mm_f16<EPI_BIAS_RESID><<<dim3(ROWS/128, DD/256), 256, GEMM_SMEM>>>(
        p_act16, p_w2p, out, b2, p_x2, ROWS, DD, FFN);
}